// round 12
// baseline (speedup 1.0000x reference)
#include <cuda_runtime.h>
#include <math.h>
#include <float.h>
#include <stdint.h>

// Problem dims: N=50000, E=800000, F_IN=128, H=128, OUT=64
#define N_MAX 50048
#define E_MAX 800064
#define ET_MAX (E_MAX + N_MAX)
#define H1 128
#define H2 64
#define NB_MAX 256   // max scan blocks (ceil(N/256) = 196)

// ---------------- scratch (device globals; no runtime allocation) ----------
__device__ float g_xl1[(size_t)N_MAX * H1];
__device__ float g_xr1[(size_t)N_MAX * H1];
__device__ float g_h  [(size_t)N_MAX * H1];
__device__ float g_xl2[(size_t)N_MAX * H2];   // private layer-2 buffers
__device__ float g_xr2[(size_t)N_MAX * H2];
__device__ uint32_t g_W1s[(size_t)H1 * 2 * (2 * H1)];  // [128][2*256] hi/lo pairs
__device__ uint32_t g_W2s[(size_t)H1 * 2 * (2 * H2)];  // [128][2*128]
__device__ unsigned long long g_stat[N_MAX];        // packed (cnt<<48)|fixsum
__device__ unsigned long long g_scanstate[NB_MAX];  // lookback: (flag<<62)|val
__device__ float g_loop[N_MAX];
__device__ int   g_rowptr[N_MAX + 1];
__device__ int   g_fill[N_MAX];
__device__ int2  g_ce[ET_MAX];                      // {col, eav-as-int}

// ---------------- tf32 split (truncation form) ------------------------------
// hi = x with mantissa bits [12:0] zeroed (tensor core reads only tf32 bits,
// so truncated-fp32 IS a valid hi operand). lo = x - hi is exact in fp32;
// its own low bits are ignored by the MMA (error ~2^-23 of x). 2 ops/element.
__device__ __forceinline__ void trunc_split(float x, uint32_t& hi, uint32_t& lo) {
    hi = __float_as_uint(x) & 0xFFFFE000u;
    lo = __float_as_uint(x - __uint_as_float(hi));
}
__device__ __forceinline__ void mma_tf32(float* c, const uint32_t* a, const uint32_t* b) {
    asm volatile(
        "mma.sync.aligned.m16n8k8.row.col.f32.tf32.tf32.f32 "
        "{%0,%1,%2,%3}, {%4,%5,%6,%7}, {%8,%9}, {%0,%1,%2,%3};"
        : "+f"(c[0]), "+f"(c[1]), "+f"(c[2]), "+f"(c[3])
        : "r"(a[0]), "r"(a[1]), "r"(a[2]), "r"(a[3]), "r"(b[0]), "r"(b[1]));
}

// Presplit combined weight matrices into interleaved (hi,lo) word pairs.
// W1s cols: [0,128)=Wl1, [128,256)=Wr1. W2s cols: [0,64)=Wl2, [64,128)=Wr2.
__global__ void presplit_kernel(const float* __restrict__ Wl1, const float* __restrict__ Wr1,
                                const float* __restrict__ Wl2, const float* __restrict__ Wr2) {
    int i = blockIdx.x * blockDim.x + threadIdx.x;
    const int N1 = H1 * 2 * H1;           // 32768 elements (k, c) for W1s
    const int N2 = H1 * 2 * H2;           // 16384 for W2s
    if (i < N1) {
        int k = i / (2 * H1), c = i % (2 * H1);
        float v = (c < H1) ? Wl1[k * H1 + c] : Wr1[k * H1 + (c - H1)];
        uint32_t hi, lo; trunc_split(v, hi, lo);
        g_W1s[(size_t)k * 2 * (2 * H1) + 2 * c]     = hi;
        g_W1s[(size_t)k * 2 * (2 * H1) + 2 * c + 1] = lo;
    } else if (i < N1 + N2) {
        int j = i - N1;
        int k = j / (2 * H2), c = j % (2 * H2);
        float v = (c < H2) ? Wl2[k * H2 + c] : Wr2[k * H2 + (c - H2)];
        uint32_t hi, lo; trunc_split(v, hi, lo);
        g_W2s[(size_t)k * 2 * (2 * H2) + 2 * c]     = hi;
        g_W2s[(size_t)k * 2 * (2 * H2) + 2 * c + 1] = lo;
    }
}

// --------- tensor-core dual GEMM (3xTF32, presplit B): C = A @ W[K,BN] ------
// grid.x selects output half (col offset in Ws, C1/C2). BM=128, BK=32,
// 512 threads, 4x4 warps (WM=32, WN=BN/4). A smem fp32 (split inline, 2 ops);
// B smem = presplit (hi,lo) pairs copied from global, inner loop = pure LDS.64.
template <int BN>
__global__ __launch_bounds__(512, 1)
void mma_gemm_kernel(const float* __restrict__ A, const uint32_t* __restrict__ Ws,
                     float* __restrict__ C1, float* __restrict__ C2,
                     int M, int K) {
    const int BM = 128, BK = 32;
    const int AS_LD = 36, BS_LD = 2 * BN + 8;
    const int ASZ = BM * AS_LD, BSZ = BK * BS_LD;
    const int WR = 4;
    const int WM = 32;
    const int WN = BN / 4;
    const int MT = 2, NT = WN / 8;        // 2,4 (BN=128) / 2,2 (BN=64)
    const int BNW = 2 * BN;               // total cols in Ws

    extern __shared__ uint32_t smem[];
    float*    As = (float*)smem;          // [2][BM][AS_LD] fp32
    uint32_t* Bs = smem + 2 * ASZ;        // [2][BK][BS_LD] (hi,lo) pairs

    int cOff = blockIdx.x * BN;
    float* C = (blockIdx.x == 0) ? C1 : C2;

    int tid = threadIdx.x;
    int warp = tid >> 5, lane = tid & 31;
    int g = lane >> 2, tg = lane & 3;
    int warpM = warp % WR, warpN = warp / WR;
    int rowBase = blockIdx.y * BM;

    auto loadTiles = [&](int buf, int k0) {
#pragma unroll
        for (int i = tid; i < BM * BK / 4; i += 512) {
            int r = i / (BK / 4), c4 = 4 * (i % (BK / 4));
            int gr = rowBase + r;
            float4 v = make_float4(0.f, 0.f, 0.f, 0.f);
            if (gr < M) v = *(const float4*)&A[(size_t)gr * K + k0 + c4];
            *(float4*)&As[buf * ASZ + r * AS_LD + c4] = v;
        }
        // B: plain copy of presplit pairs; uint4 = 2 (hi,lo) pairs = 2 cols
#pragma unroll
        for (int i = tid; i < BK * BN / 2; i += 512) {
            int r = i / (BN / 2), c2 = i % (BN / 2);
            uint4 v = *(const uint4*)&Ws[(size_t)(k0 + r) * 2 * BNW + 2 * cOff + 4 * c2];
            *(uint4*)&Bs[buf * BSZ + r * BS_LD + 4 * c2] = v;
        }
    };

    float acc[MT][NT][4];
#pragma unroll
    for (int mi = 0; mi < MT; mi++)
#pragma unroll
        for (int ni = 0; ni < NT; ni++)
#pragma unroll
            for (int q = 0; q < 4; q++) acc[mi][ni][q] = 0.f;

    int ntiles = K / BK;
    loadTiles(0, 0);
    __syncthreads();
    for (int t = 0; t < ntiles; t++) {
        int cur = t & 1;
        if (t + 1 < ntiles) loadTiles(cur ^ 1, (t + 1) * BK);
        const float*    as = &As[cur * ASZ];
        const uint32_t* bs = &Bs[cur * BSZ];
#pragma unroll
        for (int ks = 0; ks < BK / 8; ks++) {
            int kk = ks * 8;
            uint32_t ahi[MT][4], alo[MT][4];
#pragma unroll
            for (int mi = 0; mi < MT; mi++) {
                int r0 = warpM * WM + mi * 16 + g;
                trunc_split(as[r0 * AS_LD + kk + tg],           ahi[mi][0], alo[mi][0]);
                trunc_split(as[(r0 + 8) * AS_LD + kk + tg],     ahi[mi][1], alo[mi][1]);
                trunc_split(as[r0 * AS_LD + kk + tg + 4],       ahi[mi][2], alo[mi][2]);
                trunc_split(as[(r0 + 8) * AS_LD + kk + tg + 4], ahi[mi][3], alo[mi][3]);
            }
#pragma unroll
            for (int ni = 0; ni < NT; ni++) {
                int cB = warpN * WN + ni * 8 + g;
                uint2 q0 = *(const uint2*)&bs[(kk + tg) * BS_LD + 2 * cB];
                uint2 q1 = *(const uint2*)&bs[(kk + tg + 4) * BS_LD + 2 * cB];
                uint32_t bhi[2] = {q0.x, q1.x};
                uint32_t blo[2] = {q0.y, q1.y};
#pragma unroll
                for (int mi = 0; mi < MT; mi++) {
                    mma_tf32(acc[mi][ni], ahi[mi], bhi);
                    mma_tf32(acc[mi][ni], ahi[mi], blo);
                    mma_tf32(acc[mi][ni], alo[mi], bhi);
                }
            }
        }
        __syncthreads();
    }

#pragma unroll
    for (int mi = 0; mi < MT; mi++) {
#pragma unroll
        for (int ni = 0; ni < NT; ni++) {
            int row = rowBase + warpM * WM + mi * 16 + g;
            int col = warpN * WN + ni * 8 + 2 * tg;
            if (row < M)
                *(float2*)&C[(size_t)row * BN + col] =
                    make_float2(acc[mi][ni][0], acc[mi][ni][1]);
            if (row + 8 < M)
                *(float2*)&C[(size_t)(row + 8) * BN + col] =
                    make_float2(acc[mi][ni][2], acc[mi][ni][3]);
        }
    }
}

#define SMEM_M1 ((2 * 128 * 36 + 2 * 32 * (2 * 128 + 8)) * (int)sizeof(uint32_t))  // ~102KB
#define SMEM_M2 ((2 * 128 * 36 + 2 * 32 * (2 * 64 + 8))  * (int)sizeof(uint32_t))  // ~70KB

// ---------------- graph preprocessing --------------------------------------

__global__ void stats_kernel(const int* __restrict__ dst, const float* __restrict__ ea, int e) {
    int i = blockIdx.x * blockDim.x + threadIdx.x;
    if (i < e) {
        unsigned long long add =
            (1ULL << 48) | (unsigned long long)__float2ll_rn((ea[i] + 64.0f) * 16777216.0f);
        atomicAdd(&g_stat[dst[i]], add);
    }
}

// Decoupled-lookback scan of (cnt[i]+1) in one launch; decodes loop_attr.
__global__ void scan_kernel(int n, int total) {
    __shared__ int sh[256];
    __shared__ int sbase;
    int t = threadIdx.x, b = blockIdx.x;
    int i = b * 256 + t;

    unsigned long long st = (i < n) ? g_stat[i] : 0ULL;
    int cnt = (int)(st >> 48);
    int v = (i < n) ? cnt + 1 : 0;

    sh[t] = v;
    __syncthreads();
#pragma unroll
    for (int off = 1; off < 256; off <<= 1) {
        int u = (t >= off) ? sh[t - off] : 0;
        __syncthreads();
        sh[t] += u;
        __syncthreads();
    }

    if (t == 0) {
        unsigned long long agg = (unsigned long long)sh[255];
        if (b == 0) {
            atomicExch(&g_scanstate[0], (2ULL << 62) | agg);
            sbase = 0;
        } else {
            atomicExch(&g_scanstate[b], (1ULL << 62) | agg);
            long long sum = 0;
            for (int p = b - 1; p >= 0; p--) {
                unsigned long long s;
                do { s = atomicAdd(&g_scanstate[p], 0ULL); } while ((s >> 62) == 0);
                sum += (long long)(s & 0x3FFFFFFFFFFFFFFFULL);
                if ((s >> 62) == 2ULL) break;
            }
            atomicExch(&g_scanstate[b], (2ULL << 62) | (unsigned long long)(sum + (long long)agg));
            sbase = (int)sum;
        }
    }
    __syncthreads();

    if (i < n) {
        int pre = sbase + sh[t] - v;
        g_rowptr[i] = pre;
        g_fill[i]   = pre;
        double fsum = (double)(long long)(st & 0xFFFFFFFFFFFFULL) * (1.0 / 16777216.0)
                      - 64.0 * (double)cnt;
        g_loop[i] = (float)(fsum / (double)max(cnt, 1));
    }
    if (i == 0) g_rowptr[n] = total;
}

__global__ void scatter_kernel(const int* __restrict__ src, const int* __restrict__ dst,
                               const float* __restrict__ ea, int e, int n) {
    int i = blockIdx.x * blockDim.x + threadIdx.x;
    if (i < e) {
        int p = atomicAdd(&g_fill[dst[i]], 1);
        g_ce[p] = make_int2(src[i], __float_as_int(ea[i]));
    } else if (i < e + n) {
        int v = i - e;
        int p = atomicAdd(&g_fill[v], 1);
        g_ce[p] = make_int2(v, __float_as_int(g_loop[v]));
    }
}

// ---------------- fused GATv2 node kernel (warp per node, 8-edge batches) ---
template <int C>
__global__ void gat_node_kernel(const float* __restrict__ xl, const float* __restrict__ xr,
                                const float* __restrict__ We, const float* __restrict__ att,
                                const float* __restrict__ bias, float* __restrict__ out,
                                int n0, int n1) {
    const int R = C / 32;
    int warp = n0 + ((blockIdx.x * blockDim.x + threadIdx.x) >> 5);
    if (warp >= n1) return;
    int lane = threadIdx.x & 31;
    int cbase = lane * R;

    float xrv[R], wev[R], attv[R];
    if (R == 4) {
        float4 a = *(const float4*)&xr[(size_t)warp * C + cbase];
        float4 b = *(const float4*)&We[cbase];
        float4 c = *(const float4*)&att[cbase];
        xrv[0]=a.x; xrv[1]=a.y; xrv[2]=a.z; xrv[3]=a.w;
        wev[0]=b.x; wev[1]=b.y; wev[2]=b.z; wev[3]=b.w;
        attv[0]=c.x; attv[1]=c.y; attv[2]=c.z; attv[3]=c.w;
    } else {
        float2 a = *(const float2*)&xr[(size_t)warp * C + cbase];
        float2 b = *(const float2*)&We[cbase];
        float2 c = *(const float2*)&att[cbase];
        xrv[0]=a.x; xrv[1]=a.y;
        wev[0]=b.x; wev[1]=b.y;
        attv[0]=c.x; attv[1]=c.y;
    }

    float m = -FLT_MAX, s = 0.f;
    float accv[R];
#pragma unroll
    for (int r = 0; r < R; r++) accv[r] = 0.f;

    int beg = g_rowptr[warp], endp = g_rowptr[warp + 1];
    for (int e0 = beg; e0 < endp; e0 += 8) {
        int cnt = endp - e0;                      // >= 1 (self-loop)
        int jj[8]; float aa[8];
#pragma unroll
        for (int t = 0; t < 8; t++) {
            int ee = (t < cnt) ? e0 + t : e0;     // clamp: valid addr, masked below
            int2 ce = __ldg(&g_ce[ee]);
            jj[t] = ce.x;
            aa[t] = __int_as_float(ce.y);
        }
        float xlv[8][R];
#pragma unroll
        for (int t = 0; t < 8; t++) {
            if (R == 4) {
                float4 v = *(const float4*)&xl[(size_t)jj[t] * C + cbase];
                xlv[t][0]=v.x; xlv[t][1]=v.y; xlv[t][2]=v.z; xlv[t][3]=v.w;
            } else {
                float2 v = *(const float2*)&xl[(size_t)jj[t] * C + cbase];
                xlv[t][0]=v.x; xlv[t][1]=v.y;
            }
        }
        float part[8];
#pragma unroll
        for (int t = 0; t < 8; t++) {
            float p = 0.f;
#pragma unroll
            for (int r = 0; r < R; r++) {
                float z = xlv[t][r] + xrv[r] + aa[t] * wev[r];
                z = (z > 0.f) ? z : 0.2f * z;     // leaky_relu(0.2)
                p += z * attv[r];
            }
            part[t] = p;
        }
#pragma unroll
        for (int off = 16; off > 0; off >>= 1) {
#pragma unroll
            for (int t = 0; t < 8; t++)
                part[t] += __shfl_xor_sync(0xffffffffu, part[t], off);
        }
#pragma unroll
        for (int t = 0; t < 8; t++)
            if (t >= cnt) part[t] = -FLT_MAX;     // mask tail -> exp 0
        float bm = part[0];
#pragma unroll
        for (int t = 1; t < 8; t++) bm = fmaxf(bm, part[t]);
        if (bm > m) {
            float c0 = __expf(m - bm);            // exp(-inf)=0 on first batch
            s *= c0;
#pragma unroll
            for (int r = 0; r < R; r++) accv[r] *= c0;
            m = bm;
        }
#pragma unroll
        for (int t = 0; t < 8; t++) {
            float w = __expf(part[t] - m);
            s += w;
#pragma unroll
            for (int r = 0; r < R; r++) accv[r] += w * xlv[t][r];
        }
    }

    float inv = 1.0f / (s + 1e-16f);
    float o[R];
#pragma unroll
    for (int r = 0; r < R; r++) {
        float v = accv[r] * inv + bias[cbase + r];
        o[r] = (v > 0.f) ? v : expm1f(v);   // ELU
    }
    if (R == 4)
        *(float4*)&out[(size_t)warp * C + cbase] = make_float4(o[0], o[1], o[2], o[3]);
    else
        *(float2*)&out[(size_t)warp * C + cbase] = make_float2(o[0], o[1]);
}

// ---------------- host-side setup (static init, pre-baseline) ---------------
namespace {
cudaStream_t g_sB = nullptr;
cudaEvent_t  g_evFork = nullptr, g_evCSR = nullptr, g_evA = nullptr, g_evG2a = nullptr;
bool g_overlap_ok = false;
void *g_pStat = nullptr, *g_pScan = nullptr;
struct EagerLoad {
    EagerLoad() {
        cudaGetSymbolAddress(&g_pStat, g_stat);
        cudaGetSymbolAddress(&g_pScan, g_scanstate);
        cudaFuncSetAttribute((const void*)mma_gemm_kernel<128>,
                             cudaFuncAttributeMaxDynamicSharedMemorySize, SMEM_M1);
        cudaFuncSetAttribute((const void*)mma_gemm_kernel<64>,
                             cudaFuncAttributeMaxDynamicSharedMemorySize, SMEM_M2);
        bool ok = (cudaStreamCreateWithFlags(&g_sB, cudaStreamNonBlocking) == cudaSuccess);
        ok = ok && (cudaEventCreateWithFlags(&g_evFork, cudaEventDisableTiming) == cudaSuccess);
        ok = ok && (cudaEventCreateWithFlags(&g_evCSR, cudaEventDisableTiming) == cudaSuccess);
        ok = ok && (cudaEventCreateWithFlags(&g_evA, cudaEventDisableTiming) == cudaSuccess);
        ok = ok && (cudaEventCreateWithFlags(&g_evG2a, cudaEventDisableTiming) == cudaSuccess);
        g_overlap_ok = ok;
    }
};
EagerLoad eager_load_instance;
}

// ---------------- launch ----------------------------------------------------
extern "C" void kernel_launch(void* const* d_in, const int* in_sizes, int n_in,
                              void* d_out, int out_size) {
    const float* x    = (const float*)d_in[0];
    const int*   ei   = (const int*)  d_in[1];
    const float* ea   = (const float*)d_in[2];
    const float* Wl1  = (const float*)d_in[3];
    const float* Wr1  = (const float*)d_in[4];
    const float* We1  = (const float*)d_in[5];
    const float* att1 = (const float*)d_in[6];
    const float* b1   = (const float*)d_in[7];
    const float* Wl2  = (const float*)d_in[8];
    const float* Wr2  = (const float*)d_in[9];
    const float* We2  = (const float*)d_in[10];
    const float* att2 = (const float*)d_in[11];
    const float* b2   = (const float*)d_in[12];
    float* out = (float*)d_out;

    int N = in_sizes[0] / H1;       // x is [N,128]
    int E = in_sizes[1] / 2;        // edge_index is [2,E]
    const int* src = ei;
    const int* dst = ei + E;

    float *xl1, *xr1, *h, *xl2, *xr2;
    uint32_t *W1s, *W2s;
    cudaGetSymbolAddress((void**)&xl1, g_xl1);
    cudaGetSymbolAddress((void**)&xr1, g_xr1);
    cudaGetSymbolAddress((void**)&h,   g_h);
    cudaGetSymbolAddress((void**)&xl2, g_xl2);
    cudaGetSymbolAddress((void**)&xr2, g_xr2);
    cudaGetSymbolAddress((void**)&W1s, g_W1s);
    cudaGetSymbolAddress((void**)&W2s, g_W2s);

    int nb = (N + 255) / 256;
    bool ov = g_overlap_ok;
    cudaStream_t sB = ov ? g_sB : (cudaStream_t)0;
    int Nh = (N / 2 + 127) & ~127;  // half split, 128-aligned

    // --- fork: CSR build on side stream, weight presplit + GEMM-1 on main ---
    if (ov) {
        cudaEventRecord(g_evFork, 0);
        cudaStreamWaitEvent(sB, g_evFork, 0);
    }
    cudaMemsetAsync(g_pStat, 0, (size_t)N * sizeof(unsigned long long), sB);
    cudaMemsetAsync(g_pScan, 0, (size_t)NB_MAX * sizeof(unsigned long long), sB);
    stats_kernel<<<(E + 255) / 256, 256, 0, sB>>>(dst, ea, E);
    scan_kernel<<<nb, 256, 0, sB>>>(N, E + N);
    scatter_kernel<<<(E + N + 255) / 256, 256, 0, sB>>>(src, dst, ea, E, N);
    if (ov) cudaEventRecord(g_evCSR, sB);

    presplit_kernel<<<(H1 * 2 * H1 + H1 * 2 * H2 + 255) / 256, 256>>>(Wl1, Wr1, Wl2, Wr2);
    dim3 gm1(2, (N + 127) / 128);
    mma_gemm_kernel<128><<<gm1, 512, SMEM_M1>>>(x, W1s, xl1, xr1, N, H1);

    if (ov) cudaStreamWaitEvent((cudaStream_t)0, g_evCSR, 0);

    // --- layer 1 aggregate (split halves), pipelined with GEMM-2 ---
    if (ov) {
        gat_node_kernel<H1><<<(Nh + 7) / 8, 256>>>(xl1, xr1, We1, att1, b1, h, 0, Nh);
        cudaEventRecord(g_evA, 0);
        gat_node_kernel<H1><<<(N - Nh + 7) / 8, 256>>>(xl1, xr1, We1, att1, b1, h, Nh, N);

        cudaStreamWaitEvent(sB, g_evA, 0);
        dim3 gma(2, Nh / 128);
        mma_gemm_kernel<64><<<gma, 512, SMEM_M2, sB>>>(h, W2s, xl2, xr2, Nh, H1);
        cudaEventRecord(g_evG2a, sB);

        dim3 gmb(2, (N - Nh + 127) / 128);
        mma_gemm_kernel<64><<<gmb, 512, SMEM_M2>>>(
            h + (size_t)Nh * H1, W2s,
            xl2 + (size_t)Nh * H2, xr2 + (size_t)Nh * H2, N - Nh, H1);
        cudaStreamWaitEvent((cudaStream_t)0, g_evG2a, 0);
    } else {
        gat_node_kernel<H1><<<(N + 7) / 8, 256>>>(xl1, xr1, We1, att1, b1, h, 0, N);
        dim3 gm2(2, (N + 127) / 128);
        mma_gemm_kernel<64><<<gm2, 512, SMEM_M2>>>(h, W2s, xl2, xr2, N, H1);
    }

    gat_node_kernel<H2><<<(N + 7) / 8, 256>>>(xl2, xr2, We2, att2, b2, out, 0, N);
}

// round 13
// speedup vs baseline: 1.0372x; 1.0372x over previous
#include <cuda_runtime.h>
#include <math.h>
#include <float.h>
#include <stdint.h>

// Problem dims: N=50000, E=800000, F_IN=128, H=128, OUT=64
#define N_MAX 50048
#define E_MAX 800064
#define ET_MAX (E_MAX + N_MAX)
#define H1 128
#define H2 64
#define NB_MAX 256   // max scan blocks (ceil(N/256) = 196)

// ---------------- scratch (device globals; no runtime allocation) ----------
__device__ float g_xl1[(size_t)N_MAX * H1];
__device__ float g_xr1[(size_t)N_MAX * H1];
__device__ float g_h  [(size_t)N_MAX * H1];
__device__ float g_xl2[(size_t)N_MAX * H2];   // private layer-2 buffers (race fix)
__device__ float g_xr2[(size_t)N_MAX * H2];
__device__ unsigned long long g_stat[N_MAX];        // packed (cnt<<48)|fixsum
__device__ unsigned long long g_scanstate[NB_MAX];  // lookback: (flag<<62)|val
__device__ float g_loop[N_MAX];
__device__ int   g_rowptr[N_MAX + 1];
__device__ int   g_fill[N_MAX];
__device__ int2  g_ce[ET_MAX];                      // {col, eav-as-int}

// ---------------- tf32 mma helpers (R7-proven form) -------------------------
__device__ __forceinline__ uint32_t f2tf32(float x) {
    uint32_t r;
    asm("cvt.rna.tf32.f32 %0, %1;" : "=r"(r) : "f"(x));
    return r;
}
__device__ __forceinline__ void tf32_split(float x, uint32_t& hi, uint32_t& lo) {
    hi = f2tf32(x);
    lo = f2tf32(x - __uint_as_float(hi));
}
__device__ __forceinline__ void mma_tf32(float* c, const uint32_t* a, const uint32_t* b) {
    asm volatile(
        "mma.sync.aligned.m16n8k8.row.col.f32.tf32.tf32.f32 "
        "{%0,%1,%2,%3}, {%4,%5,%6,%7}, {%8,%9}, {%0,%1,%2,%3};"
        : "+f"(c[0]), "+f"(c[1]), "+f"(c[2]), "+f"(c[3])
        : "r"(a[0]), "r"(a[1]), "r"(a[2]), "r"(a[3]), "r"(b[0]), "r"(b[1]));
}

// --------- tensor-core dual GEMM (3xTF32) — EXACT R7 configuration ----------
// grid.x selects (B1->C1) or (B2->C2). BM=128, BK=32, 256 threads (8 warps).
// BN=128: warps 2x4 (WM=64,WN=32); BN=64: warps 4x2 (WM=32,WN=32).
template <int BN>
__global__ __launch_bounds__(256, 1)
void mma_gemm_kernel(const float* __restrict__ A,
                     const float* __restrict__ B1, const float* __restrict__ B2,
                     float* __restrict__ C1, float* __restrict__ C2,
                     int M, int K) {
    const int BM = 128, BK = 32;
    const int AS_LD = 36, BS_LD = BN + 8;
    const int ASZ = BM * AS_LD, BSZ = BK * BS_LD;
    const int WR = (BN == 128) ? 2 : 4;
    const int WM = BM / WR;
    const int WN = 32;
    const int MT = WM / 16, NT = WN / 8;

    extern __shared__ float smem[];
    float* As = smem;
    float* Bs = smem + 2 * ASZ;

    const float* B = (blockIdx.x == 0) ? B1 : B2;
    float*       C = (blockIdx.x == 0) ? C1 : C2;

    int tid = threadIdx.x;
    int warp = tid >> 5, lane = tid & 31;
    int g = lane >> 2, tg = lane & 3;
    int warpM = warp % WR, warpN = warp / WR;
    int rowBase = blockIdx.y * BM;

    auto loadTiles = [&](int buf, int k0) {
#pragma unroll
        for (int i = tid; i < BM * BK / 4; i += 256) {
            int r = i / (BK / 4), c4 = 4 * (i % (BK / 4));
            int gr = rowBase + r;
            float4 v = make_float4(0.f, 0.f, 0.f, 0.f);
            if (gr < M) v = *(const float4*)&A[(size_t)gr * K + k0 + c4];
            *(float4*)&As[buf * ASZ + r * AS_LD + c4] = v;
        }
#pragma unroll
        for (int i = tid; i < BK * BN / 4; i += 256) {
            int r = i / (BN / 4), c4 = 4 * (i % (BN / 4));
            float4 v = *(const float4*)&B[(size_t)(k0 + r) * BN + c4];
            *(float4*)&Bs[buf * BSZ + r * BS_LD + c4] = v;
        }
    };

    float acc[MT][NT][4];
#pragma unroll
    for (int mi = 0; mi < MT; mi++)
#pragma unroll
        for (int ni = 0; ni < NT; ni++)
#pragma unroll
            for (int q = 0; q < 4; q++) acc[mi][ni][q] = 0.f;

    int ntiles = K / BK;
    loadTiles(0, 0);
    __syncthreads();
    for (int t = 0; t < ntiles; t++) {
        int cur = t & 1;
        if (t + 1 < ntiles) loadTiles(cur ^ 1, (t + 1) * BK);
        const float* as = &As[cur * ASZ];
        const float* bs = &Bs[cur * BSZ];
#pragma unroll
        for (int ks = 0; ks < BK / 8; ks++) {
            int kk = ks * 8;
            uint32_t ahi[MT][4], alo[MT][4];
#pragma unroll
            for (int mi = 0; mi < MT; mi++) {
                int r0 = warpM * WM + mi * 16 + g;
                tf32_split(as[r0 * AS_LD + kk + tg],           ahi[mi][0], alo[mi][0]);
                tf32_split(as[(r0 + 8) * AS_LD + kk + tg],     ahi[mi][1], alo[mi][1]);
                tf32_split(as[r0 * AS_LD + kk + tg + 4],       ahi[mi][2], alo[mi][2]);
                tf32_split(as[(r0 + 8) * AS_LD + kk + tg + 4], ahi[mi][3], alo[mi][3]);
            }
#pragma unroll
            for (int ni = 0; ni < NT; ni++) {
                int cB = warpN * WN + ni * 8 + g;
                uint32_t bhi[2], blo[2];
                tf32_split(bs[(kk + tg) * BS_LD + cB],     bhi[0], blo[0]);
                tf32_split(bs[(kk + tg + 4) * BS_LD + cB], bhi[1], blo[1]);
#pragma unroll
                for (int mi = 0; mi < MT; mi++) {
                    mma_tf32(acc[mi][ni], ahi[mi], bhi);
                    mma_tf32(acc[mi][ni], ahi[mi], blo);
                    mma_tf32(acc[mi][ni], alo[mi], bhi);
                }
            }
        }
        __syncthreads();
    }

#pragma unroll
    for (int mi = 0; mi < MT; mi++) {
#pragma unroll
        for (int ni = 0; ni < NT; ni++) {
            int row = rowBase + warpM * WM + mi * 16 + g;
            int col = warpN * WN + ni * 8 + 2 * tg;
            if (row < M)
                *(float2*)&C[(size_t)row * BN + col] =
                    make_float2(acc[mi][ni][0], acc[mi][ni][1]);
            if (row + 8 < M)
                *(float2*)&C[(size_t)(row + 8) * BN + col] =
                    make_float2(acc[mi][ni][2], acc[mi][ni][3]);
        }
    }
}

#define SMEM_M1 ((2 * 128 * 36 + 2 * 32 * 136) * (int)sizeof(float))  // ~70KB
#define SMEM_M2 ((2 * 128 * 36 + 2 * 32 * 72)  * (int)sizeof(float))  // ~55KB

// ---------------- graph preprocessing --------------------------------------

__global__ void stats_kernel(const int* __restrict__ dst, const float* __restrict__ ea, int e) {
    int i = blockIdx.x * blockDim.x + threadIdx.x;
    if (i < e) {
        unsigned long long add =
            (1ULL << 48) | (unsigned long long)__float2ll_rn((ea[i] + 64.0f) * 16777216.0f);
        atomicAdd(&g_stat[dst[i]], add);
    }
}

// Decoupled-lookback scan of (cnt[i]+1) in one launch; decodes loop_attr.
__global__ void scan_kernel(int n, int total) {
    __shared__ int sh[256];
    __shared__ int sbase;
    int t = threadIdx.x, b = blockIdx.x;
    int i = b * 256 + t;

    unsigned long long st = (i < n) ? g_stat[i] : 0ULL;
    int cnt = (int)(st >> 48);
    int v = (i < n) ? cnt + 1 : 0;

    sh[t] = v;
    __syncthreads();
#pragma unroll
    for (int off = 1; off < 256; off <<= 1) {
        int u = (t >= off) ? sh[t - off] : 0;
        __syncthreads();
        sh[t] += u;
        __syncthreads();
    }

    if (t == 0) {
        unsigned long long agg = (unsigned long long)sh[255];
        if (b == 0) {
            atomicExch(&g_scanstate[0], (2ULL << 62) | agg);
            sbase = 0;
        } else {
            atomicExch(&g_scanstate[b], (1ULL << 62) | agg);
            long long sum = 0;
            for (int p = b - 1; p >= 0; p--) {
                unsigned long long s;
                do { s = atomicAdd(&g_scanstate[p], 0ULL); } while ((s >> 62) == 0);
                sum += (long long)(s & 0x3FFFFFFFFFFFFFFFULL);
                if ((s >> 62) == 2ULL) break;
            }
            atomicExch(&g_scanstate[b], (2ULL << 62) | (unsigned long long)(sum + (long long)agg));
            sbase = (int)sum;
        }
    }
    __syncthreads();

    if (i < n) {
        int pre = sbase + sh[t] - v;
        g_rowptr[i] = pre;
        g_fill[i]   = pre;
        double fsum = (double)(long long)(st & 0xFFFFFFFFFFFFULL) * (1.0 / 16777216.0)
                      - 64.0 * (double)cnt;
        g_loop[i] = (float)(fsum / (double)max(cnt, 1));
    }
    if (i == 0) g_rowptr[n] = total;
}

__global__ void scatter_kernel(const int* __restrict__ src, const int* __restrict__ dst,
                               const float* __restrict__ ea, int e, int n) {
    int i = blockIdx.x * blockDim.x + threadIdx.x;
    if (i < e) {
        int p = atomicAdd(&g_fill[dst[i]], 1);
        g_ce[p] = make_int2(src[i], __float_as_int(ea[i]));
    } else if (i < e + n) {
        int v = i - e;
        int p = atomicAdd(&g_fill[v], 1);
        g_ce[p] = make_int2(v, __float_as_int(g_loop[v]));
    }
}

// ---------------- fused GATv2 node kernel (warp per node, 8-edge batches) ---
template <int C>
__global__ void gat_node_kernel(const float* __restrict__ xl, const float* __restrict__ xr,
                                const float* __restrict__ We, const float* __restrict__ att,
                                const float* __restrict__ bias, float* __restrict__ out,
                                int n0, int n1) {
    const int R = C / 32;
    int warp = n0 + ((blockIdx.x * blockDim.x + threadIdx.x) >> 5);
    if (warp >= n1) return;
    int lane = threadIdx.x & 31;
    int cbase = lane * R;

    float xrv[R], wev[R], attv[R];
    if (R == 4) {
        float4 a = *(const float4*)&xr[(size_t)warp * C + cbase];
        float4 b = *(const float4*)&We[cbase];
        float4 c = *(const float4*)&att[cbase];
        xrv[0]=a.x; xrv[1]=a.y; xrv[2]=a.z; xrv[3]=a.w;
        wev[0]=b.x; wev[1]=b.y; wev[2]=b.z; wev[3]=b.w;
        attv[0]=c.x; attv[1]=c.y; attv[2]=c.z; attv[3]=c.w;
    } else {
        float2 a = *(const float2*)&xr[(size_t)warp * C + cbase];
        float2 b = *(const float2*)&We[cbase];
        float2 c = *(const float2*)&att[cbase];
        xrv[0]=a.x; xrv[1]=a.y;
        wev[0]=b.x; wev[1]=b.y;
        attv[0]=c.x; attv[1]=c.y;
    }

    float m = -FLT_MAX, s = 0.f;
    float accv[R];
#pragma unroll
    for (int r = 0; r < R; r++) accv[r] = 0.f;

    int beg = g_rowptr[warp], endp = g_rowptr[warp + 1];
    for (int e0 = beg; e0 < endp; e0 += 8) {
        int cnt = endp - e0;                      // >= 1 (self-loop)
        int jj[8]; float aa[8];
#pragma unroll
        for (int t = 0; t < 8; t++) {
            int ee = (t < cnt) ? e0 + t : e0;     // clamp: valid addr, masked below
            int2 ce = __ldg(&g_ce[ee]);
            jj[t] = ce.x;
            aa[t] = __int_as_float(ce.y);
        }
        float xlv[8][R];
#pragma unroll
        for (int t = 0; t < 8; t++) {
            if (R == 4) {
                float4 v = *(const float4*)&xl[(size_t)jj[t] * C + cbase];
                xlv[t][0]=v.x; xlv[t][1]=v.y; xlv[t][2]=v.z; xlv[t][3]=v.w;
            } else {
                float2 v = *(const float2*)&xl[(size_t)jj[t] * C + cbase];
                xlv[t][0]=v.x; xlv[t][1]=v.y;
            }
        }
        float part[8];
#pragma unroll
        for (int t = 0; t < 8; t++) {
            float p = 0.f;
#pragma unroll
            for (int r = 0; r < R; r++) {
                float z = xlv[t][r] + xrv[r] + aa[t] * wev[r];
                z = (z > 0.f) ? z : 0.2f * z;     // leaky_relu(0.2)
                p += z * attv[r];
            }
            part[t] = p;
        }
#pragma unroll
        for (int off = 16; off > 0; off >>= 1) {
#pragma unroll
            for (int t = 0; t < 8; t++)
                part[t] += __shfl_xor_sync(0xffffffffu, part[t], off);
        }
#pragma unroll
        for (int t = 0; t < 8; t++)
            if (t >= cnt) part[t] = -FLT_MAX;     // mask tail -> exp 0
        float bm = part[0];
#pragma unroll
        for (int t = 1; t < 8; t++) bm = fmaxf(bm, part[t]);
        if (bm > m) {
            float c0 = __expf(m - bm);            // exp(-inf)=0 on first batch
            s *= c0;
#pragma unroll
            for (int r = 0; r < R; r++) accv[r] *= c0;
            m = bm;
        }
#pragma unroll
        for (int t = 0; t < 8; t++) {
            float w = __expf(part[t] - m);
            s += w;
#pragma unroll
            for (int r = 0; r < R; r++) accv[r] += w * xlv[t][r];
        }
    }

    float inv = 1.0f / (s + 1e-16f);
    float o[R];
#pragma unroll
    for (int r = 0; r < R; r++) {
        float v = accv[r] * inv + bias[cbase + r];
        o[r] = (v > 0.f) ? v : expm1f(v);   // ELU
    }
    if (R == 4)
        *(float4*)&out[(size_t)warp * C + cbase] = make_float4(o[0], o[1], o[2], o[3]);
    else
        *(float2*)&out[(size_t)warp * C + cbase] = make_float2(o[0], o[1]);
}

// ---------------- host-side setup (static init, pre-baseline) ---------------
namespace {
cudaStream_t g_sB = nullptr;
cudaEvent_t  g_evFork = nullptr, g_evCSR = nullptr, g_evA = nullptr, g_evG2a = nullptr;
bool g_overlap_ok = false;
void *g_pStat = nullptr, *g_pScan = nullptr;
struct EagerLoad {
    EagerLoad() {
        cudaGetSymbolAddress(&g_pStat, g_stat);
        cudaGetSymbolAddress(&g_pScan, g_scanstate);
        cudaFuncSetAttribute((const void*)mma_gemm_kernel<128>,
                             cudaFuncAttributeMaxDynamicSharedMemorySize, SMEM_M1);
        cudaFuncSetAttribute((const void*)mma_gemm_kernel<64>,
                             cudaFuncAttributeMaxDynamicSharedMemorySize, SMEM_M2);
        bool ok = (cudaStreamCreateWithFlags(&g_sB, cudaStreamNonBlocking) == cudaSuccess);
        ok = ok && (cudaEventCreateWithFlags(&g_evFork, cudaEventDisableTiming) == cudaSuccess);
        ok = ok && (cudaEventCreateWithFlags(&g_evCSR, cudaEventDisableTiming) == cudaSuccess);
        ok = ok && (cudaEventCreateWithFlags(&g_evA, cudaEventDisableTiming) == cudaSuccess);
        ok = ok && (cudaEventCreateWithFlags(&g_evG2a, cudaEventDisableTiming) == cudaSuccess);
        g_overlap_ok = ok;
    }
};
EagerLoad eager_load_instance;
}

// ---------------- launch ----------------------------------------------------
extern "C" void kernel_launch(void* const* d_in, const int* in_sizes, int n_in,
                              void* d_out, int out_size) {
    const float* x    = (const float*)d_in[0];
    const int*   ei   = (const int*)  d_in[1];
    const float* ea   = (const float*)d_in[2];
    const float* Wl1  = (const float*)d_in[3];
    const float* Wr1  = (const float*)d_in[4];
    const float* We1  = (const float*)d_in[5];
    const float* att1 = (const float*)d_in[6];
    const float* b1   = (const float*)d_in[7];
    const float* Wl2  = (const float*)d_in[8];
    const float* Wr2  = (const float*)d_in[9];
    const float* We2  = (const float*)d_in[10];
    const float* att2 = (const float*)d_in[11];
    const float* b2   = (const float*)d_in[12];
    float* out = (float*)d_out;

    int N = in_sizes[0] / H1;       // x is [N,128]
    int E = in_sizes[1] / 2;        // edge_index is [2,E]
    const int* src = ei;
    const int* dst = ei + E;

    float *xl1, *xr1, *h, *xl2, *xr2;
    cudaGetSymbolAddress((void**)&xl1, g_xl1);
    cudaGetSymbolAddress((void**)&xr1, g_xr1);
    cudaGetSymbolAddress((void**)&h,   g_h);
    cudaGetSymbolAddress((void**)&xl2, g_xl2);
    cudaGetSymbolAddress((void**)&xr2, g_xr2);

    int nb = (N + 255) / 256;
    bool ov = g_overlap_ok;
    cudaStream_t sB = ov ? g_sB : (cudaStream_t)0;
    int Nh = (N / 2 + 127) & ~127;  // half split, 128-aligned

    // --- fork: CSR build on side stream, GEMM-1 on main ---
    if (ov) {
        cudaEventRecord(g_evFork, 0);
        cudaStreamWaitEvent(sB, g_evFork, 0);
    }
    cudaMemsetAsync(g_pStat, 0, (size_t)N * sizeof(unsigned long long), sB);
    cudaMemsetAsync(g_pScan, 0, (size_t)NB_MAX * sizeof(unsigned long long), sB);
    stats_kernel<<<(E + 255) / 256, 256, 0, sB>>>(dst, ea, E);
    scan_kernel<<<nb, 256, 0, sB>>>(N, E + N);
    scatter_kernel<<<(E + N + 255) / 256, 256, 0, sB>>>(src, dst, ea, E, N);
    if (ov) cudaEventRecord(g_evCSR, sB);

    dim3 gm1(2, (N + 127) / 128);
    mma_gemm_kernel<128><<<gm1, 256, SMEM_M1>>>(x, Wl1, Wr1, xl1, xr1, N, H1);

    if (ov) cudaStreamWaitEvent((cudaStream_t)0, g_evCSR, 0);

    // --- layer 1 aggregate (split halves), pipelined with GEMM-2 ---
    if (ov) {
        gat_node_kernel<H1><<<(Nh + 7) / 8, 256>>>(xl1, xr1, We1, att1, b1, h, 0, Nh);
        cudaEventRecord(g_evA, 0);
        gat_node_kernel<H1><<<(N - Nh + 7) / 8, 256>>>(xl1, xr1, We1, att1, b1, h, Nh, N);

        cudaStreamWaitEvent(sB, g_evA, 0);
        dim3 gma(2, Nh / 128);
        mma_gemm_kernel<64><<<gma, 256, SMEM_M2, sB>>>(h, Wl2, Wr2, xl2, xr2, Nh, H1);
        cudaEventRecord(g_evG2a, sB);

        dim3 gmb(2, (N - Nh + 127) / 128);
        mma_gemm_kernel<64><<<gmb, 256, SMEM_M2>>>(
            h + (size_t)Nh * H1, Wl2, Wr2,
            xl2 + (size_t)Nh * H2, xr2 + (size_t)Nh * H2, N - Nh, H1);
        cudaStreamWaitEvent((cudaStream_t)0, g_evG2a, 0);
    } else {
        gat_node_kernel<H1><<<(N + 7) / 8, 256>>>(xl1, xr1, We1, att1, b1, h, 0, N);
        dim3 gm2(2, (N + 127) / 128);
        mma_gemm_kernel<64><<<gm2, 256, SMEM_M2>>>(h, Wl2, Wr2, xl2, xr2, N, H1);
    }

    gat_node_kernel<H2><<<(N + 7) / 8, 256>>>(xl2, xr2, We2, att2, b2, out, 0, N);
}

// round 14
// speedup vs baseline: 1.2204x; 1.1766x over previous
#include <cuda_runtime.h>
#include <math.h>
#include <float.h>
#include <stdint.h>

// Problem dims: N=50000, E=800000, F_IN=128, H=128, OUT=64
#define N_MAX 50048
#define E_MAX 800064
#define ET_MAX (E_MAX + N_MAX)
#define H1 128
#define H2 64
#define NB_MAX 256   // max scan blocks (ceil(N/256) = 196)

// ---------------- scratch (device globals; no runtime allocation) ----------
__device__ float g_xl1[(size_t)N_MAX * H1];
__device__ float g_xr1[(size_t)N_MAX * H1];
__device__ float g_h  [(size_t)N_MAX * H1];
__device__ float g_xl2[(size_t)N_MAX * H2];   // private layer-2 buffers (race fix)
__device__ float g_xr2[(size_t)N_MAX * H2];
// combined: [0,N_MAX) packed (cnt<<48)|fixsum ; [N_MAX, N_MAX+NB_MAX) lookback state
__device__ unsigned long long g_stat[N_MAX + NB_MAX];
__device__ float g_loop[N_MAX];
__device__ int   g_rowptr[N_MAX + 1];
__device__ int   g_fill[N_MAX];
__device__ int2  g_ce[ET_MAX];                      // {col, eav-as-int}

// ---------------- tf32 mma helpers (R7-proven form) -------------------------
__device__ __forceinline__ uint32_t f2tf32(float x) {
    uint32_t r;
    asm("cvt.rna.tf32.f32 %0, %1;" : "=r"(r) : "f"(x));
    return r;
}
__device__ __forceinline__ void tf32_split(float x, uint32_t& hi, uint32_t& lo) {
    hi = f2tf32(x);
    lo = f2tf32(x - __uint_as_float(hi));
}
__device__ __forceinline__ void mma_tf32(float* c, const uint32_t* a, const uint32_t* b) {
    asm volatile(
        "mma.sync.aligned.m16n8k8.row.col.f32.tf32.tf32.f32 "
        "{%0,%1,%2,%3}, {%4,%5,%6,%7}, {%8,%9}, {%0,%1,%2,%3};"
        : "+f"(c[0]), "+f"(c[1]), "+f"(c[2]), "+f"(c[3])
        : "r"(a[0]), "r"(a[1]), "r"(a[2]), "r"(a[3]), "r"(b[0]), "r"(b[1]));
}

// --------- tensor-core dual GEMM (3xTF32) — EXACT R7 configuration ----------
template <int BN>
__global__ __launch_bounds__(256, 1)
void mma_gemm_kernel(const float* __restrict__ A,
                     const float* __restrict__ B1, const float* __restrict__ B2,
                     float* __restrict__ C1, float* __restrict__ C2,
                     int M, int K) {
    const int BM = 128, BK = 32;
    const int AS_LD = 36, BS_LD = BN + 8;
    const int ASZ = BM * AS_LD, BSZ = BK * BS_LD;
    const int WR = (BN == 128) ? 2 : 4;
    const int WM = BM / WR;
    const int WN = 32;
    const int MT = WM / 16, NT = WN / 8;

    extern __shared__ float smem[];
    float* As = smem;
    float* Bs = smem + 2 * ASZ;

    const float* B = (blockIdx.x == 0) ? B1 : B2;
    float*       C = (blockIdx.x == 0) ? C1 : C2;

    int tid = threadIdx.x;
    int warp = tid >> 5, lane = tid & 31;
    int g = lane >> 2, tg = lane & 3;
    int warpM = warp % WR, warpN = warp / WR;
    int rowBase = blockIdx.y * BM;

    auto loadTiles = [&](int buf, int k0) {
#pragma unroll
        for (int i = tid; i < BM * BK / 4; i += 256) {
            int r = i / (BK / 4), c4 = 4 * (i % (BK / 4));
            int gr = rowBase + r;
            float4 v = make_float4(0.f, 0.f, 0.f, 0.f);
            if (gr < M) v = *(const float4*)&A[(size_t)gr * K + k0 + c4];
            *(float4*)&As[buf * ASZ + r * AS_LD + c4] = v;
        }
#pragma unroll
        for (int i = tid; i < BK * BN / 4; i += 256) {
            int r = i / (BN / 4), c4 = 4 * (i % (BN / 4));
            float4 v = *(const float4*)&B[(size_t)(k0 + r) * BN + c4];
            *(float4*)&Bs[buf * BSZ + r * BS_LD + c4] = v;
        }
    };

    float acc[MT][NT][4];
#pragma unroll
    for (int mi = 0; mi < MT; mi++)
#pragma unroll
        for (int ni = 0; ni < NT; ni++)
#pragma unroll
            for (int q = 0; q < 4; q++) acc[mi][ni][q] = 0.f;

    int ntiles = K / BK;
    loadTiles(0, 0);
    __syncthreads();
    for (int t = 0; t < ntiles; t++) {
        int cur = t & 1;
        if (t + 1 < ntiles) loadTiles(cur ^ 1, (t + 1) * BK);
        const float* as = &As[cur * ASZ];
        const float* bs = &Bs[cur * BSZ];
#pragma unroll
        for (int ks = 0; ks < BK / 8; ks++) {
            int kk = ks * 8;
            uint32_t ahi[MT][4], alo[MT][4];
#pragma unroll
            for (int mi = 0; mi < MT; mi++) {
                int r0 = warpM * WM + mi * 16 + g;
                tf32_split(as[r0 * AS_LD + kk + tg],           ahi[mi][0], alo[mi][0]);
                tf32_split(as[(r0 + 8) * AS_LD + kk + tg],     ahi[mi][1], alo[mi][1]);
                tf32_split(as[r0 * AS_LD + kk + tg + 4],       ahi[mi][2], alo[mi][2]);
                tf32_split(as[(r0 + 8) * AS_LD + kk + tg + 4], ahi[mi][3], alo[mi][3]);
            }
#pragma unroll
            for (int ni = 0; ni < NT; ni++) {
                int cB = warpN * WN + ni * 8 + g;
                uint32_t bhi[2], blo[2];
                tf32_split(bs[(kk + tg) * BS_LD + cB],     bhi[0], blo[0]);
                tf32_split(bs[(kk + tg + 4) * BS_LD + cB], bhi[1], blo[1]);
#pragma unroll
                for (int mi = 0; mi < MT; mi++) {
                    mma_tf32(acc[mi][ni], ahi[mi], bhi);
                    mma_tf32(acc[mi][ni], ahi[mi], blo);
                    mma_tf32(acc[mi][ni], alo[mi], bhi);
                }
            }
        }
        __syncthreads();
    }

#pragma unroll
    for (int mi = 0; mi < MT; mi++) {
#pragma unroll
        for (int ni = 0; ni < NT; ni++) {
            int row = rowBase + warpM * WM + mi * 16 + g;
            int col = warpN * WN + ni * 8 + 2 * tg;
            if (row < M)
                *(float2*)&C[(size_t)row * BN + col] =
                    make_float2(acc[mi][ni][0], acc[mi][ni][1]);
            if (row + 8 < M)
                *(float2*)&C[(size_t)(row + 8) * BN + col] =
                    make_float2(acc[mi][ni][2], acc[mi][ni][3]);
        }
    }
}

#define SMEM_M1 ((2 * 128 * 36 + 2 * 32 * 136) * (int)sizeof(float))  // ~70KB
#define SMEM_M2 ((2 * 128 * 36 + 2 * 32 * 72)  * (int)sizeof(float))  // ~55KB

// ---------------- graph preprocessing --------------------------------------

__global__ void stats_kernel(const int* __restrict__ dst, const float* __restrict__ ea, int e) {
    int i = blockIdx.x * blockDim.x + threadIdx.x;
    if (i < e) {
        unsigned long long add =
            (1ULL << 48) | (unsigned long long)__float2ll_rn((ea[i] + 64.0f) * 16777216.0f);
        atomicAdd(&g_stat[dst[i]], add);
    }
}

// Decoupled-lookback scan of (cnt[i]+1) in one launch; decodes loop_attr.
// Lookback state lives at g_stat + N_MAX (zeroed by the same memset).
__global__ void scan_kernel(int n, int total) {
    unsigned long long* scanstate = g_stat + N_MAX;
    __shared__ int sh[256];
    __shared__ int sbase;
    int t = threadIdx.x, b = blockIdx.x;
    int i = b * 256 + t;

    unsigned long long st = (i < n) ? g_stat[i] : 0ULL;
    int cnt = (int)(st >> 48);
    int v = (i < n) ? cnt + 1 : 0;

    sh[t] = v;
    __syncthreads();
#pragma unroll
    for (int off = 1; off < 256; off <<= 1) {
        int u = (t >= off) ? sh[t - off] : 0;
        __syncthreads();
        sh[t] += u;
        __syncthreads();
    }

    if (t == 0) {
        unsigned long long agg = (unsigned long long)sh[255];
        if (b == 0) {
            atomicExch(&scanstate[0], (2ULL << 62) | agg);
            sbase = 0;
        } else {
            atomicExch(&scanstate[b], (1ULL << 62) | agg);
            long long sum = 0;
            for (int p = b - 1; p >= 0; p--) {
                unsigned long long s;
                do { s = atomicAdd(&scanstate[p], 0ULL); } while ((s >> 62) == 0);
                sum += (long long)(s & 0x3FFFFFFFFFFFFFFFULL);
                if ((s >> 62) == 2ULL) break;
            }
            atomicExch(&scanstate[b], (2ULL << 62) | (unsigned long long)(sum + (long long)agg));
            sbase = (int)sum;
        }
    }
    __syncthreads();

    if (i < n) {
        int pre = sbase + sh[t] - v;
        g_rowptr[i] = pre;
        g_fill[i]   = pre;
        double fsum = (double)(long long)(st & 0xFFFFFFFFFFFFULL) * (1.0 / 16777216.0)
                      - 64.0 * (double)cnt;
        g_loop[i] = (float)(fsum / (double)max(cnt, 1));
    }
    if (i == 0) g_rowptr[n] = total;
}

__global__ void scatter_kernel(const int* __restrict__ src, const int* __restrict__ dst,
                               const float* __restrict__ ea, int e, int n) {
    int i = blockIdx.x * blockDim.x + threadIdx.x;
    if (i < e) {
        int p = atomicAdd(&g_fill[dst[i]], 1);
        g_ce[p] = make_int2(src[i], __float_as_int(ea[i]));
    } else if (i < e + n) {
        int v = i - e;
        int p = atomicAdd(&g_fill[v], 1);
        g_ce[p] = make_int2(v, __float_as_int(g_loop[v]));
    }
}

// ---------------- fused GATv2 node kernel (warp per node, 4-edge batches) ---
template <int C>
__global__ void gat_node_kernel(const float* __restrict__ xl, const float* __restrict__ xr,
                                const float* __restrict__ We, const float* __restrict__ att,
                                const float* __restrict__ bias, float* __restrict__ out,
                                int n0, int n1) {
    const int R = C / 32;
    int warp = n0 + ((blockIdx.x * blockDim.x + threadIdx.x) >> 5);
    if (warp >= n1) return;
    int lane = threadIdx.x & 31;
    int cbase = lane * R;

    float xrv[R], wev[R], attv[R];
    if (R == 4) {
        float4 a = *(const float4*)&xr[(size_t)warp * C + cbase];
        float4 b = *(const float4*)&We[cbase];
        float4 c = *(const float4*)&att[cbase];
        xrv[0]=a.x; xrv[1]=a.y; xrv[2]=a.z; xrv[3]=a.w;
        wev[0]=b.x; wev[1]=b.y; wev[2]=b.z; wev[3]=b.w;
        attv[0]=c.x; attv[1]=c.y; attv[2]=c.z; attv[3]=c.w;
    } else {
        float2 a = *(const float2*)&xr[(size_t)warp * C + cbase];
        float2 b = *(const float2*)&We[cbase];
        float2 c = *(const float2*)&att[cbase];
        xrv[0]=a.x; xrv[1]=a.y;
        wev[0]=b.x; wev[1]=b.y;
        attv[0]=c.x; attv[1]=c.y;
    }

    float m = -FLT_MAX, s = 0.f;
    float accv[R];
#pragma unroll
    for (int r = 0; r < R; r++) accv[r] = 0.f;

    int beg = g_rowptr[warp], endp = g_rowptr[warp + 1];
    for (int e0 = beg; e0 < endp; e0 += 4) {
        int cnt = endp - e0;
        int jj[4]; float aa[4];
#pragma unroll
        for (int t = 0; t < 4; t++) {
            int ee = (t < cnt) ? e0 + t : e0;
            int2 ce = __ldg(&g_ce[ee]);
            jj[t] = ce.x;
            aa[t] = __int_as_float(ce.y);
        }
        float xlv[4][R];
#pragma unroll
        for (int t = 0; t < 4; t++) {
            if (R == 4) {
                float4 v = *(const float4*)&xl[(size_t)jj[t] * C + cbase];
                xlv[t][0]=v.x; xlv[t][1]=v.y; xlv[t][2]=v.z; xlv[t][3]=v.w;
            } else {
                float2 v = *(const float2*)&xl[(size_t)jj[t] * C + cbase];
                xlv[t][0]=v.x; xlv[t][1]=v.y;
            }
        }
        float part[4];
#pragma unroll
        for (int t = 0; t < 4; t++) {
            float p = 0.f;
#pragma unroll
            for (int r = 0; r < R; r++) {
                float z = xlv[t][r] + xrv[r] + aa[t] * wev[r];
                z = (z > 0.f) ? z : 0.2f * z;     // leaky_relu(0.2)
                p += z * attv[r];
            }
            part[t] = p;
        }
#pragma unroll
        for (int off = 16; off > 0; off >>= 1) {
#pragma unroll
            for (int t = 0; t < 4; t++)
                part[t] += __shfl_xor_sync(0xffffffffu, part[t], off);
        }
#pragma unroll
        for (int t = 0; t < 4; t++)
            if (t >= cnt) part[t] = -FLT_MAX;
        float bm = fmaxf(fmaxf(part[0], part[1]), fmaxf(part[2], part[3]));
        if (bm > m) {
            float c0 = __expf(m - bm);
            s *= c0;
#pragma unroll
            for (int r = 0; r < R; r++) accv[r] *= c0;
            m = bm;
        }
#pragma unroll
        for (int t = 0; t < 4; t++) {
            float w = __expf(part[t] - m);
            s += w;
#pragma unroll
            for (int r = 0; r < R; r++) accv[r] += w * xlv[t][r];
        }
    }

    float inv = 1.0f / (s + 1e-16f);
    float o[R];
#pragma unroll
    for (int r = 0; r < R; r++) {
        float v = accv[r] * inv + bias[cbase + r];
        o[r] = (v > 0.f) ? v : (__expf(v) - 1.0f);   // ELU (fast exp)
    }
    if (R == 4)
        *(float4*)&out[(size_t)warp * C + cbase] = make_float4(o[0], o[1], o[2], o[3]);
    else
        *(float2*)&out[(size_t)warp * C + cbase] = make_float2(o[0], o[1]);
}

// ---------------- host-side setup (static init, pre-baseline) ---------------
namespace {
cudaStream_t g_sB = nullptr;
cudaEvent_t  g_evFork = nullptr, g_evCSR = nullptr, g_evA = nullptr, g_evG2a = nullptr;
bool g_overlap_ok = false;
void *g_pStat = nullptr;
struct EagerLoad {
    EagerLoad() {
        cudaGetSymbolAddress(&g_pStat, g_stat);
        cudaFuncSetAttribute((const void*)mma_gemm_kernel<128>,
                             cudaFuncAttributeMaxDynamicSharedMemorySize, SMEM_M1);
        cudaFuncSetAttribute((const void*)mma_gemm_kernel<64>,
                             cudaFuncAttributeMaxDynamicSharedMemorySize, SMEM_M2);
        bool ok = (cudaStreamCreateWithFlags(&g_sB, cudaStreamNonBlocking) == cudaSuccess);
        ok = ok && (cudaEventCreateWithFlags(&g_evFork, cudaEventDisableTiming) == cudaSuccess);
        ok = ok && (cudaEventCreateWithFlags(&g_evCSR, cudaEventDisableTiming) == cudaSuccess);
        ok = ok && (cudaEventCreateWithFlags(&g_evA, cudaEventDisableTiming) == cudaSuccess);
        ok = ok && (cudaEventCreateWithFlags(&g_evG2a, cudaEventDisableTiming) == cudaSuccess);
        g_overlap_ok = ok;
    }
};
EagerLoad eager_load_instance;
}

// ---------------- launch ----------------------------------------------------
extern "C" void kernel_launch(void* const* d_in, const int* in_sizes, int n_in,
                              void* d_out, int out_size) {
    const float* x    = (const float*)d_in[0];
    const int*   ei   = (const int*)  d_in[1];
    const float* ea   = (const float*)d_in[2];
    const float* Wl1  = (const float*)d_in[3];
    const float* Wr1  = (const float*)d_in[4];
    const float* We1  = (const float*)d_in[5];
    const float* att1 = (const float*)d_in[6];
    const float* b1   = (const float*)d_in[7];
    const float* Wl2  = (const float*)d_in[8];
    const float* Wr2  = (const float*)d_in[9];
    const float* We2  = (const float*)d_in[10];
    const float* att2 = (const float*)d_in[11];
    const float* b2   = (const float*)d_in[12];
    float* out = (float*)d_out;

    int N = in_sizes[0] / H1;       // x is [N,128]
    int E = in_sizes[1] / 2;        // edge_index is [2,E]
    const int* src = ei;
    const int* dst = ei + E;

    float *xl1, *xr1, *h, *xl2, *xr2;
    cudaGetSymbolAddress((void**)&xl1, g_xl1);
    cudaGetSymbolAddress((void**)&xr1, g_xr1);
    cudaGetSymbolAddress((void**)&h,   g_h);
    cudaGetSymbolAddress((void**)&xl2, g_xl2);
    cudaGetSymbolAddress((void**)&xr2, g_xr2);

    int nb = (N + 255) / 256;
    bool ov = g_overlap_ok;
    cudaStream_t sB = ov ? g_sB : (cudaStream_t)0;
    int Nh = (N / 2 + 127) & ~127;  // half split, 128-aligned

    // --- fork: CSR build on side stream, GEMM-1 on main ---
    if (ov) {
        cudaEventRecord(g_evFork, 0);
        cudaStreamWaitEvent(sB, g_evFork, 0);
    }
    // one memset covers stats + lookback state (contiguous in g_stat)
    cudaMemsetAsync(g_pStat, 0, (size_t)(N_MAX + NB_MAX) * sizeof(unsigned long long), sB);
    stats_kernel<<<(E + 255) / 256, 256, 0, sB>>>(dst, ea, E);
    scan_kernel<<<nb, 256, 0, sB>>>(N, E + N);
    scatter_kernel<<<(E + N + 255) / 256, 256, 0, sB>>>(src, dst, ea, E, N);
    if (ov) cudaEventRecord(g_evCSR, sB);

    dim3 gm1(2, (N + 127) / 128);
    mma_gemm_kernel<128><<<gm1, 256, SMEM_M1>>>(x, Wl1, Wr1, xl1, xr1, N, H1);

    if (ov) cudaStreamWaitEvent((cudaStream_t)0, g_evCSR, 0);

    // --- layer 1 aggregate (split halves), pipelined with GEMM-2 ---
    if (ov) {
        gat_node_kernel<H1><<<(Nh + 7) / 8, 256>>>(xl1, xr1, We1, att1, b1, h, 0, Nh);
        cudaEventRecord(g_evA, 0);
        gat_node_kernel<H1><<<(N - Nh + 7) / 8, 256>>>(xl1, xr1, We1, att1, b1, h, Nh, N);

        cudaStreamWaitEvent(sB, g_evA, 0);
        dim3 gma(2, Nh / 128);
        mma_gemm_kernel<64><<<gma, 256, SMEM_M2, sB>>>(h, Wl2, Wr2, xl2, xr2, Nh, H1);
        cudaEventRecord(g_evG2a, sB);

        dim3 gmb(2, (N - Nh + 127) / 128);
        mma_gemm_kernel<64><<<gmb, 256, SMEM_M2>>>(
            h + (size_t)Nh * H1, Wl2, Wr2,
            xl2 + (size_t)Nh * H2, xr2 + (size_t)Nh * H2, N - Nh, H1);
        cudaStreamWaitEvent((cudaStream_t)0, g_evG2a, 0);
    } else {
        gat_node_kernel<H1><<<(N + 7) / 8, 256>>>(xl1, xr1, We1, att1, b1, h, 0, N);
        dim3 gm2(2, (N + 127) / 128);
        mma_gemm_kernel<64><<<gm2, 256, SMEM_M2>>>(h, Wl2, Wr2, xl2, xr2, N, H1);
    }

    gat_node_kernel<H2><<<(N + 7) / 8, 256>>>(xl2, xr2, We2, att2, b2, out, 0, N);
}

// round 15
// speedup vs baseline: 1.2251x; 1.0039x over previous
#include <cuda_runtime.h>
#include <math.h>
#include <float.h>
#include <stdint.h>

// Problem dims: N=50000, E=800000, F_IN=128, H=128, OUT=64
#define N_MAX 50048
#define E_MAX 800064
#define ET_MAX (E_MAX + N_MAX)
#define H1 128
#define H2 64
#define NB_MAX 256   // max scan blocks (ceil(N/256) = 196)

// ---------------- scratch (device globals; no runtime allocation) ----------
__device__ float g_xl1[(size_t)N_MAX * H1];
__device__ float g_xr1[(size_t)N_MAX * H1];
__device__ float g_h  [(size_t)N_MAX * H1];
__device__ float g_xl2[(size_t)N_MAX * H2];   // private layer-2 buffers (race fix)
__device__ float g_xr2[(size_t)N_MAX * H2];
// combined: [0,N_MAX) packed (cnt<<48)|fixsum ; [N_MAX, N_MAX+NB_MAX) lookback state
__device__ unsigned long long g_stat[N_MAX + NB_MAX];
__device__ float g_loop[N_MAX];
__device__ int   g_rowptr[N_MAX + 1];
__device__ int   g_fill[N_MAX];
__device__ int2  g_ce[ET_MAX];                      // {col, eav-as-int}

// ---------------- tf32 mma helpers (R7-proven form) -------------------------
__device__ __forceinline__ uint32_t f2tf32(float x) {
    uint32_t r;
    asm("cvt.rna.tf32.f32 %0, %1;" : "=r"(r) : "f"(x));
    return r;
}
__device__ __forceinline__ void tf32_split(float x, uint32_t& hi, uint32_t& lo) {
    hi = f2tf32(x);
    lo = f2tf32(x - __uint_as_float(hi));
}
__device__ __forceinline__ void mma_tf32(float* c, const uint32_t* a, const uint32_t* b) {
    asm volatile(
        "mma.sync.aligned.m16n8k8.row.col.f32.tf32.tf32.f32 "
        "{%0,%1,%2,%3}, {%4,%5,%6,%7}, {%8,%9}, {%0,%1,%2,%3};"
        : "+f"(c[0]), "+f"(c[1]), "+f"(c[2]), "+f"(c[3])
        : "r"(a[0]), "r"(a[1]), "r"(a[2]), "r"(a[3]), "r"(b[0]), "r"(b[1]));
}

// --------- tensor-core dual GEMM (3xTF32) — EXACT R7 configuration ----------
template <int BN>
__global__ __launch_bounds__(256, 1)
void mma_gemm_kernel(const float* __restrict__ A,
                     const float* __restrict__ B1, const float* __restrict__ B2,
                     float* __restrict__ C1, float* __restrict__ C2,
                     int M, int K) {
    const int BM = 128, BK = 32;
    const int AS_LD = 36, BS_LD = BN + 8;
    const int ASZ = BM * AS_LD, BSZ = BK * BS_LD;
    const int WR = (BN == 128) ? 2 : 4;
    const int WM = BM / WR;
    const int WN = 32;
    const int MT = WM / 16, NT = WN / 8;

    extern __shared__ float smem[];
    float* As = smem;
    float* Bs = smem + 2 * ASZ;

    const float* B = (blockIdx.x == 0) ? B1 : B2;
    float*       C = (blockIdx.x == 0) ? C1 : C2;

    int tid = threadIdx.x;
    int warp = tid >> 5, lane = tid & 31;
    int g = lane >> 2, tg = lane & 3;
    int warpM = warp % WR, warpN = warp / WR;
    int rowBase = blockIdx.y * BM;

    auto loadTiles = [&](int buf, int k0) {
#pragma unroll
        for (int i = tid; i < BM * BK / 4; i += 256) {
            int r = i / (BK / 4), c4 = 4 * (i % (BK / 4));
            int gr = rowBase + r;
            float4 v = make_float4(0.f, 0.f, 0.f, 0.f);
            if (gr < M) v = *(const float4*)&A[(size_t)gr * K + k0 + c4];
            *(float4*)&As[buf * ASZ + r * AS_LD + c4] = v;
        }
#pragma unroll
        for (int i = tid; i < BK * BN / 4; i += 256) {
            int r = i / (BN / 4), c4 = 4 * (i % (BN / 4));
            float4 v = *(const float4*)&B[(size_t)(k0 + r) * BN + c4];
            *(float4*)&Bs[buf * BSZ + r * BS_LD + c4] = v;
        }
    };

    float acc[MT][NT][4];
#pragma unroll
    for (int mi = 0; mi < MT; mi++)
#pragma unroll
        for (int ni = 0; ni < NT; ni++)
#pragma unroll
            for (int q = 0; q < 4; q++) acc[mi][ni][q] = 0.f;

    int ntiles = K / BK;
    loadTiles(0, 0);
    __syncthreads();
    for (int t = 0; t < ntiles; t++) {
        int cur = t & 1;
        if (t + 1 < ntiles) loadTiles(cur ^ 1, (t + 1) * BK);
        const float* as = &As[cur * ASZ];
        const float* bs = &Bs[cur * BSZ];
#pragma unroll
        for (int ks = 0; ks < BK / 8; ks++) {
            int kk = ks * 8;
            uint32_t ahi[MT][4], alo[MT][4];
#pragma unroll
            for (int mi = 0; mi < MT; mi++) {
                int r0 = warpM * WM + mi * 16 + g;
                tf32_split(as[r0 * AS_LD + kk + tg],           ahi[mi][0], alo[mi][0]);
                tf32_split(as[(r0 + 8) * AS_LD + kk + tg],     ahi[mi][1], alo[mi][1]);
                tf32_split(as[r0 * AS_LD + kk + tg + 4],       ahi[mi][2], alo[mi][2]);
                tf32_split(as[(r0 + 8) * AS_LD + kk + tg + 4], ahi[mi][3], alo[mi][3]);
            }
#pragma unroll
            for (int ni = 0; ni < NT; ni++) {
                int cB = warpN * WN + ni * 8 + g;
                uint32_t bhi[2], blo[2];
                tf32_split(bs[(kk + tg) * BS_LD + cB],     bhi[0], blo[0]);
                tf32_split(bs[(kk + tg + 4) * BS_LD + cB], bhi[1], blo[1]);
#pragma unroll
                for (int mi = 0; mi < MT; mi++) {
                    mma_tf32(acc[mi][ni], ahi[mi], bhi);
                    mma_tf32(acc[mi][ni], ahi[mi], blo);
                    mma_tf32(acc[mi][ni], alo[mi], bhi);
                }
            }
        }
        __syncthreads();
    }

#pragma unroll
    for (int mi = 0; mi < MT; mi++) {
#pragma unroll
        for (int ni = 0; ni < NT; ni++) {
            int row = rowBase + warpM * WM + mi * 16 + g;
            int col = warpN * WN + ni * 8 + 2 * tg;
            if (row < M)
                *(float2*)&C[(size_t)row * BN + col] =
                    make_float2(acc[mi][ni][0], acc[mi][ni][1]);
            if (row + 8 < M)
                *(float2*)&C[(size_t)(row + 8) * BN + col] =
                    make_float2(acc[mi][ni][2], acc[mi][ni][3]);
        }
    }
}

#define SMEM_M1 ((2 * 128 * 36 + 2 * 32 * 136) * (int)sizeof(float))  // ~70KB
#define SMEM_M2 ((2 * 128 * 36 + 2 * 32 * 72)  * (int)sizeof(float))  // ~55KB

// ---------------- graph preprocessing --------------------------------------

__global__ void stats_kernel(const int* __restrict__ dst, const float* __restrict__ ea, int e) {
    int i = blockIdx.x * blockDim.x + threadIdx.x;
    if (i < e) {
        unsigned long long add =
            (1ULL << 48) | (unsigned long long)__float2ll_rn((ea[i] + 64.0f) * 16777216.0f);
        atomicAdd(&g_stat[dst[i]], add);
    }
}

// Decoupled-lookback scan of (cnt[i]+1) in one launch; decodes loop_attr.
// Lookback state lives at g_stat + N_MAX (zeroed by the same memset).
__global__ void scan_kernel(int n, int total) {
    unsigned long long* scanstate = g_stat + N_MAX;
    __shared__ int sh[256];
    __shared__ int sbase;
    int t = threadIdx.x, b = blockIdx.x;
    int i = b * 256 + t;

    unsigned long long st = (i < n) ? g_stat[i] : 0ULL;
    int cnt = (int)(st >> 48);
    int v = (i < n) ? cnt + 1 : 0;

    sh[t] = v;
    __syncthreads();
#pragma unroll
    for (int off = 1; off < 256; off <<= 1) {
        int u = (t >= off) ? sh[t - off] : 0;
        __syncthreads();
        sh[t] += u;
        __syncthreads();
    }

    if (t == 0) {
        unsigned long long agg = (unsigned long long)sh[255];
        if (b == 0) {
            atomicExch(&scanstate[0], (2ULL << 62) | agg);
            sbase = 0;
        } else {
            atomicExch(&scanstate[b], (1ULL << 62) | agg);
            long long sum = 0;
            for (int p = b - 1; p >= 0; p--) {
                unsigned long long s;
                do { s = atomicAdd(&scanstate[p], 0ULL); } while ((s >> 62) == 0);
                sum += (long long)(s & 0x3FFFFFFFFFFFFFFFULL);
                if ((s >> 62) == 2ULL) break;
            }
            atomicExch(&scanstate[b], (2ULL << 62) | (unsigned long long)(sum + (long long)agg));
            sbase = (int)sum;
        }
    }
    __syncthreads();

    if (i < n) {
        int pre = sbase + sh[t] - v;
        g_rowptr[i] = pre;
        g_fill[i]   = pre;
        double fsum = (double)(long long)(st & 0xFFFFFFFFFFFFULL) * (1.0 / 16777216.0)
                      - 64.0 * (double)cnt;
        g_loop[i] = (float)(fsum / (double)max(cnt, 1));
    }
    if (i == 0) g_rowptr[n] = total;
}

__global__ void scatter_kernel(const int* __restrict__ src, const int* __restrict__ dst,
                               const float* __restrict__ ea, int e, int n) {
    int i = blockIdx.x * blockDim.x + threadIdx.x;
    if (i < e) {
        int p = atomicAdd(&g_fill[dst[i]], 1);
        g_ce[p] = make_int2(src[i], __float_as_int(ea[i]));
    } else if (i < e + n) {
        int v = i - e;
        int p = atomicAdd(&g_fill[v], 1);
        g_ce[p] = make_int2(v, __float_as_int(g_loop[v]));
    }
}

// ---------------- fused GATv2 node kernel (warp per node, 4-edge batches) ---
template <int C>
__global__ void gat_node_kernel(const float* __restrict__ xl, const float* __restrict__ xr,
                                const float* __restrict__ We, const float* __restrict__ att,
                                const float* __restrict__ bias, float* __restrict__ out,
                                int n0, int n1) {
    const int R = C / 32;
    int warp = n0 + ((blockIdx.x * blockDim.x + threadIdx.x) >> 5);
    if (warp >= n1) return;
    int lane = threadIdx.x & 31;
    int cbase = lane * R;

    float xrv[R], wev[R], attv[R];
    if (R == 4) {
        float4 a = *(const float4*)&xr[(size_t)warp * C + cbase];
        float4 b = *(const float4*)&We[cbase];
        float4 c = *(const float4*)&att[cbase];
        xrv[0]=a.x; xrv[1]=a.y; xrv[2]=a.z; xrv[3]=a.w;
        wev[0]=b.x; wev[1]=b.y; wev[2]=b.z; wev[3]=b.w;
        attv[0]=c.x; attv[1]=c.y; attv[2]=c.z; attv[3]=c.w;
    } else {
        float2 a = *(const float2*)&xr[(size_t)warp * C + cbase];
        float2 b = *(const float2*)&We[cbase];
        float2 c = *(const float2*)&att[cbase];
        xrv[0]=a.x; xrv[1]=a.y;
        wev[0]=b.x; wev[1]=b.y;
        attv[0]=c.x; attv[1]=c.y;
    }

    float m = -FLT_MAX, s = 0.f;
    float accv[R];
#pragma unroll
    for (int r = 0; r < R; r++) accv[r] = 0.f;

    int beg = g_rowptr[warp], endp = g_rowptr[warp + 1];
    for (int e0 = beg; e0 < endp; e0 += 4) {
        int cnt = endp - e0;
        int jj[4]; float aa[4];
#pragma unroll
        for (int t = 0; t < 4; t++) {
            int ee = (t < cnt) ? e0 + t : e0;
            int2 ce = __ldg(&g_ce[ee]);
            jj[t] = ce.x;
            aa[t] = __int_as_float(ce.y);
        }
        float xlv[4][R];
#pragma unroll
        for (int t = 0; t < 4; t++) {
            if (R == 4) {
                float4 v = *(const float4*)&xl[(size_t)jj[t] * C + cbase];
                xlv[t][0]=v.x; xlv[t][1]=v.y; xlv[t][2]=v.z; xlv[t][3]=v.w;
            } else {
                float2 v = *(const float2*)&xl[(size_t)jj[t] * C + cbase];
                xlv[t][0]=v.x; xlv[t][1]=v.y;
            }
        }
        float part[4];
#pragma unroll
        for (int t = 0; t < 4; t++) {
            float p = 0.f;
#pragma unroll
            for (int r = 0; r < R; r++) {
                float z = xlv[t][r] + xrv[r] + aa[t] * wev[r];
                z = (z > 0.f) ? z : 0.2f * z;     // leaky_relu(0.2)
                p += z * attv[r];
            }
            part[t] = p;
        }
#pragma unroll
        for (int off = 16; off > 0; off >>= 1) {
#pragma unroll
            for (int t = 0; t < 4; t++)
                part[t] += __shfl_xor_sync(0xffffffffu, part[t], off);
        }
#pragma unroll
        for (int t = 0; t < 4; t++)
            if (t >= cnt) part[t] = -FLT_MAX;
        float bm = fmaxf(fmaxf(part[0], part[1]), fmaxf(part[2], part[3]));
        if (bm > m) {
            float c0 = __expf(m - bm);
            s *= c0;
#pragma unroll
            for (int r = 0; r < R; r++) accv[r] *= c0;
            m = bm;
        }
#pragma unroll
        for (int t = 0; t < 4; t++) {
            float w = __expf(part[t] - m);
            s += w;
#pragma unroll
            for (int r = 0; r < R; r++) accv[r] += w * xlv[t][r];
        }
    }

    float inv = 1.0f / (s + 1e-16f);
    float o[R];
#pragma unroll
    for (int r = 0; r < R; r++) {
        float v = accv[r] * inv + bias[cbase + r];
        o[r] = (v > 0.f) ? v : (__expf(v) - 1.0f);   // ELU (fast exp)
    }
    if (R == 4)
        *(float4*)&out[(size_t)warp * C + cbase] = make_float4(o[0], o[1], o[2], o[3]);
    else
        *(float2*)&out[(size_t)warp * C + cbase] = make_float2(o[0], o[1]);
}

// ---------------- host-side setup (static init, pre-baseline) ---------------
namespace {
cudaStream_t g_sB = nullptr;
cudaEvent_t  g_evFork = nullptr, g_evCSR = nullptr, g_evA = nullptr, g_evG2a = nullptr;
bool g_overlap_ok = false;
void *g_pStat = nullptr;
struct EagerLoad {
    EagerLoad() {
        cudaGetSymbolAddress(&g_pStat, g_stat);
        cudaFuncSetAttribute((const void*)mma_gemm_kernel<128>,
                             cudaFuncAttributeMaxDynamicSharedMemorySize, SMEM_M1);
        cudaFuncSetAttribute((const void*)mma_gemm_kernel<64>,
                             cudaFuncAttributeMaxDynamicSharedMemorySize, SMEM_M2);
        bool ok = (cudaStreamCreateWithFlags(&g_sB, cudaStreamNonBlocking) == cudaSuccess);
        ok = ok && (cudaEventCreateWithFlags(&g_evFork, cudaEventDisableTiming) == cudaSuccess);
        ok = ok && (cudaEventCreateWithFlags(&g_evCSR, cudaEventDisableTiming) == cudaSuccess);
        ok = ok && (cudaEventCreateWithFlags(&g_evA, cudaEventDisableTiming) == cudaSuccess);
        ok = ok && (cudaEventCreateWithFlags(&g_evG2a, cudaEventDisableTiming) == cudaSuccess);
        g_overlap_ok = ok;
    }
};
EagerLoad eager_load_instance;
}

// ---------------- launch ----------------------------------------------------
extern "C" void kernel_launch(void* const* d_in, const int* in_sizes, int n_in,
                              void* d_out, int out_size) {
    const float* x    = (const float*)d_in[0];
    const int*   ei   = (const int*)  d_in[1];
    const float* ea   = (const float*)d_in[2];
    const float* Wl1  = (const float*)d_in[3];
    const float* Wr1  = (const float*)d_in[4];
    const float* We1  = (const float*)d_in[5];
    const float* att1 = (const float*)d_in[6];
    const float* b1   = (const float*)d_in[7];
    const float* Wl2  = (const float*)d_in[8];
    const float* Wr2  = (const float*)d_in[9];
    const float* We2  = (const float*)d_in[10];
    const float* att2 = (const float*)d_in[11];
    const float* b2   = (const float*)d_in[12];
    float* out = (float*)d_out;

    int N = in_sizes[0] / H1;       // x is [N,128]
    int E = in_sizes[1] / 2;        // edge_index is [2,E]
    const int* src = ei;
    const int* dst = ei + E;

    float *xl1, *xr1, *h, *xl2, *xr2;
    cudaGetSymbolAddress((void**)&xl1, g_xl1);
    cudaGetSymbolAddress((void**)&xr1, g_xr1);
    cudaGetSymbolAddress((void**)&h,   g_h);
    cudaGetSymbolAddress((void**)&xl2, g_xl2);
    cudaGetSymbolAddress((void**)&xr2, g_xr2);

    int nb = (N + 255) / 256;
    bool ov = g_overlap_ok;
    cudaStream_t sB = ov ? g_sB : (cudaStream_t)0;
    int Nh = (N / 2 + 127) & ~127;  // half split, 128-aligned

    // --- fork: CSR build on side stream, GEMM-1 on main ---
    if (ov) {
        cudaEventRecord(g_evFork, 0);
        cudaStreamWaitEvent(sB, g_evFork, 0);
    }
    // one memset covers stats + lookback state (contiguous in g_stat)
    cudaMemsetAsync(g_pStat, 0, (size_t)(N_MAX + NB_MAX) * sizeof(unsigned long long), sB);
    stats_kernel<<<(E + 255) / 256, 256, 0, sB>>>(dst, ea, E);
    scan_kernel<<<nb, 256, 0, sB>>>(N, E + N);
    scatter_kernel<<<(E + N + 255) / 256, 256, 0, sB>>>(src, dst, ea, E, N);
    if (ov) cudaEventRecord(g_evCSR, sB);

    dim3 gm1(2, (N + 127) / 128);
    mma_gemm_kernel<128><<<gm1, 256, SMEM_M1>>>(x, Wl1, Wr1, xl1, xr1, N, H1);

    if (ov) cudaStreamWaitEvent((cudaStream_t)0, g_evCSR, 0);

    // --- layer 1 aggregate (split halves), pipelined with GEMM-2 ---
    if (ov) {
        gat_node_kernel<H1><<<(Nh + 7) / 8, 256>>>(xl1, xr1, We1, att1, b1, h, 0, Nh);
        cudaEventRecord(g_evA, 0);
        gat_node_kernel<H1><<<(N - Nh + 7) / 8, 256>>>(xl1, xr1, We1, att1, b1, h, Nh, N);

        cudaStreamWaitEvent(sB, g_evA, 0);
        dim3 gma(2, Nh / 128);
        mma_gemm_kernel<64><<<gma, 256, SMEM_M2, sB>>>(h, Wl2, Wr2, xl2, xr2, Nh, H1);
        cudaEventRecord(g_evG2a, sB);

        dim3 gmb(2, (N - Nh + 127) / 128);
        mma_gemm_kernel<64><<<gmb, 256, SMEM_M2>>>(
            h + (size_t)Nh * H1, Wl2, Wr2,
            xl2 + (size_t)Nh * H2, xr2 + (size_t)Nh * H2, N - Nh, H1);
        cudaStreamWaitEvent((cudaStream_t)0, g_evG2a, 0);
    } else {
        gat_node_kernel<H1><<<(N + 7) / 8, 256>>>(xl1, xr1, We1, att1, b1, h, 0, N);
        dim3 gm2(2, (N + 127) / 128);
        mma_gemm_kernel<64><<<gm2, 256, SMEM_M2>>>(h, Wl2, Wr2, xl2, xr2, N, H1);
    }

    gat_node_kernel<H2><<<(N + 7) / 8, 256>>>(xl2, xr2, We2, att2, b2, out, 0, N);
}

// round 16
// speedup vs baseline: 1.2265x; 1.0011x over previous
#include <cuda_runtime.h>
#include <math.h>
#include <float.h>
#include <stdint.h>

// Problem dims: N=50000, E=800000, F_IN=128, H=128, OUT=64
#define N_MAX 50048
#define E_MAX 800064
#define ET_MAX (E_MAX + N_MAX)
#define H1 128
#define H2 64
#define NB_MAX 256   // max scan blocks (ceil(N/256) = 196)

// ---------------- scratch (device globals; no runtime allocation) ----------
__device__ float g_xl1[(size_t)N_MAX * H1];
__device__ float g_xr1[(size_t)N_MAX * H1];
__device__ float g_h  [(size_t)N_MAX * H1];
__device__ float g_xl2[(size_t)N_MAX * H2];   // private layer-2 buffers (race fix)
__device__ float g_xr2[(size_t)N_MAX * H2];
// combined: [0,N_MAX) packed (cnt<<48)|fixsum ; [N_MAX, N_MAX+NB_MAX) lookback state
__device__ unsigned long long g_stat[N_MAX + NB_MAX];
__device__ float g_loop[N_MAX];
__device__ int   g_rowptr[N_MAX + 1];
__device__ int   g_fill[N_MAX];
__device__ int2  g_ce[ET_MAX];                      // {col, eav-as-int}

// ---------------- tf32 mma helpers (R7-proven form) -------------------------
__device__ __forceinline__ uint32_t f2tf32(float x) {
    uint32_t r;
    asm("cvt.rna.tf32.f32 %0, %1;" : "=r"(r) : "f"(x));
    return r;
}
__device__ __forceinline__ void tf32_split(float x, uint32_t& hi, uint32_t& lo) {
    hi = f2tf32(x);
    lo = f2tf32(x - __uint_as_float(hi));
}
__device__ __forceinline__ void mma_tf32(float* c, const uint32_t* a, const uint32_t* b) {
    asm volatile(
        "mma.sync.aligned.m16n8k8.row.col.f32.tf32.tf32.f32 "
        "{%0,%1,%2,%3}, {%4,%5,%6,%7}, {%8,%9}, {%0,%1,%2,%3};"
        : "+f"(c[0]), "+f"(c[1]), "+f"(c[2]), "+f"(c[3])
        : "r"(a[0]), "r"(a[1]), "r"(a[2]), "r"(a[3]), "r"(b[0]), "r"(b[1]));
}

// --------- tensor-core dual GEMM (3xTF32) — EXACT R7 configuration ----------
template <int BN>
__global__ __launch_bounds__(256, 1)
void mma_gemm_kernel(const float* __restrict__ A,
                     const float* __restrict__ B1, const float* __restrict__ B2,
                     float* __restrict__ C1, float* __restrict__ C2,
                     int M, int K) {
    const int BM = 128, BK = 32;
    const int AS_LD = 36, BS_LD = BN + 8;
    const int ASZ = BM * AS_LD, BSZ = BK * BS_LD;
    const int WR = (BN == 128) ? 2 : 4;
    const int WM = BM / WR;
    const int WN = 32;
    const int MT = WM / 16, NT = WN / 8;

    extern __shared__ float smem[];
    float* As = smem;
    float* Bs = smem + 2 * ASZ;

    const float* B = (blockIdx.x == 0) ? B1 : B2;
    float*       C = (blockIdx.x == 0) ? C1 : C2;

    int tid = threadIdx.x;
    int warp = tid >> 5, lane = tid & 31;
    int g = lane >> 2, tg = lane & 3;
    int warpM = warp % WR, warpN = warp / WR;
    int rowBase = blockIdx.y * BM;

    auto loadTiles = [&](int buf, int k0) {
#pragma unroll
        for (int i = tid; i < BM * BK / 4; i += 256) {
            int r = i / (BK / 4), c4 = 4 * (i % (BK / 4));
            int gr = rowBase + r;
            float4 v = make_float4(0.f, 0.f, 0.f, 0.f);
            if (gr < M) v = *(const float4*)&A[(size_t)gr * K + k0 + c4];
            *(float4*)&As[buf * ASZ + r * AS_LD + c4] = v;
        }
#pragma unroll
        for (int i = tid; i < BK * BN / 4; i += 256) {
            int r = i / (BN / 4), c4 = 4 * (i % (BN / 4));
            float4 v = *(const float4*)&B[(size_t)(k0 + r) * BN + c4];
            *(float4*)&Bs[buf * BSZ + r * BS_LD + c4] = v;
        }
    };

    float acc[MT][NT][4];
#pragma unroll
    for (int mi = 0; mi < MT; mi++)
#pragma unroll
        for (int ni = 0; ni < NT; ni++)
#pragma unroll
            for (int q = 0; q < 4; q++) acc[mi][ni][q] = 0.f;

    int ntiles = K / BK;
    loadTiles(0, 0);
    __syncthreads();
    for (int t = 0; t < ntiles; t++) {
        int cur = t & 1;
        if (t + 1 < ntiles) loadTiles(cur ^ 1, (t + 1) * BK);
        const float* as = &As[cur * ASZ];
        const float* bs = &Bs[cur * BSZ];
#pragma unroll
        for (int ks = 0; ks < BK / 8; ks++) {
            int kk = ks * 8;
            uint32_t ahi[MT][4], alo[MT][4];
#pragma unroll
            for (int mi = 0; mi < MT; mi++) {
                int r0 = warpM * WM + mi * 16 + g;
                tf32_split(as[r0 * AS_LD + kk + tg],           ahi[mi][0], alo[mi][0]);
                tf32_split(as[(r0 + 8) * AS_LD + kk + tg],     ahi[mi][1], alo[mi][1]);
                tf32_split(as[r0 * AS_LD + kk + tg + 4],       ahi[mi][2], alo[mi][2]);
                tf32_split(as[(r0 + 8) * AS_LD + kk + tg + 4], ahi[mi][3], alo[mi][3]);
            }
#pragma unroll
            for (int ni = 0; ni < NT; ni++) {
                int cB = warpN * WN + ni * 8 + g;
                uint32_t bhi[2], blo[2];
                tf32_split(bs[(kk + tg) * BS_LD + cB],     bhi[0], blo[0]);
                tf32_split(bs[(kk + tg + 4) * BS_LD + cB], bhi[1], blo[1]);
#pragma unroll
                for (int mi = 0; mi < MT; mi++) {
                    mma_tf32(acc[mi][ni], ahi[mi], bhi);
                    mma_tf32(acc[mi][ni], ahi[mi], blo);
                    mma_tf32(acc[mi][ni], alo[mi], bhi);
                }
            }
        }
        __syncthreads();
    }

#pragma unroll
    for (int mi = 0; mi < MT; mi++) {
#pragma unroll
        for (int ni = 0; ni < NT; ni++) {
            int row = rowBase + warpM * WM + mi * 16 + g;
            int col = warpN * WN + ni * 8 + 2 * tg;
            if (row < M)
                *(float2*)&C[(size_t)row * BN + col] =
                    make_float2(acc[mi][ni][0], acc[mi][ni][1]);
            if (row + 8 < M)
                *(float2*)&C[(size_t)(row + 8) * BN + col] =
                    make_float2(acc[mi][ni][2], acc[mi][ni][3]);
        }
    }
}

#define SMEM_M1 ((2 * 128 * 36 + 2 * 32 * 136) * (int)sizeof(float))  // ~70KB
#define SMEM_M2 ((2 * 128 * 36 + 2 * 32 * 72)  * (int)sizeof(float))  // ~55KB

// ---------------- graph preprocessing --------------------------------------

__global__ void stats_kernel(const int* __restrict__ dst, const float* __restrict__ ea, int e) {
    int i = blockIdx.x * blockDim.x + threadIdx.x;
    if (i < e) {
        unsigned long long add =
            (1ULL << 48) | (unsigned long long)__float2ll_rn((ea[i] + 64.0f) * 16777216.0f);
        atomicAdd(&g_stat[dst[i]], add);
    }
}

// Decoupled-lookback scan of (cnt[i]+1) in one launch; decodes loop_attr.
// Lookback state lives at g_stat + N_MAX (zeroed by the same memset).
__global__ void scan_kernel(int n, int total) {
    unsigned long long* scanstate = g_stat + N_MAX;
    __shared__ int sh[256];
    __shared__ int sbase;
    int t = threadIdx.x, b = blockIdx.x;
    int i = b * 256 + t;

    unsigned long long st = (i < n) ? g_stat[i] : 0ULL;
    int cnt = (int)(st >> 48);
    int v = (i < n) ? cnt + 1 : 0;

    sh[t] = v;
    __syncthreads();
#pragma unroll
    for (int off = 1; off < 256; off <<= 1) {
        int u = (t >= off) ? sh[t - off] : 0;
        __syncthreads();
        sh[t] += u;
        __syncthreads();
    }

    if (t == 0) {
        unsigned long long agg = (unsigned long long)sh[255];
        if (b == 0) {
            atomicExch(&scanstate[0], (2ULL << 62) | agg);
            sbase = 0;
        } else {
            atomicExch(&scanstate[b], (1ULL << 62) | agg);
            long long sum = 0;
            for (int p = b - 1; p >= 0; p--) {
                unsigned long long s;
                do { s = atomicAdd(&scanstate[p], 0ULL); } while ((s >> 62) == 0);
                sum += (long long)(s & 0x3FFFFFFFFFFFFFFFULL);
                if ((s >> 62) == 2ULL) break;
            }
            atomicExch(&scanstate[b], (2ULL << 62) | (unsigned long long)(sum + (long long)agg));
            sbase = (int)sum;
        }
    }
    __syncthreads();

    if (i < n) {
        int pre = sbase + sh[t] - v;
        g_rowptr[i] = pre;
        g_fill[i]   = pre;
        double fsum = (double)(long long)(st & 0xFFFFFFFFFFFFULL) * (1.0 / 16777216.0)
                      - 64.0 * (double)cnt;
        g_loop[i] = (float)(fsum / (double)max(cnt, 1));
    }
    if (i == 0) g_rowptr[n] = total;
}

__global__ void scatter_kernel(const int* __restrict__ src, const int* __restrict__ dst,
                               const float* __restrict__ ea, int e, int n) {
    int i = blockIdx.x * blockDim.x + threadIdx.x;
    if (i < e) {
        int p = atomicAdd(&g_fill[dst[i]], 1);
        g_ce[p] = make_int2(src[i], __float_as_int(ea[i]));
    } else if (i < e + n) {
        int v = i - e;
        int p = atomicAdd(&g_fill[v], 1);
        g_ce[p] = make_int2(v, __float_as_int(g_loop[v]));
    }
}

// ---------------- fused GATv2 node kernel (warp per node, 4-edge batches) ---
template <int C>
__global__ void gat_node_kernel(const float* __restrict__ xl, const float* __restrict__ xr,
                                const float* __restrict__ We, const float* __restrict__ att,
                                const float* __restrict__ bias, float* __restrict__ out,
                                int n0, int n1) {
    const int R = C / 32;
    int warp = n0 + ((blockIdx.x * blockDim.x + threadIdx.x) >> 5);
    if (warp >= n1) return;
    int lane = threadIdx.x & 31;
    int cbase = lane * R;

    float xrv[R], wev[R], attv[R];
    if (R == 4) {
        float4 a = *(const float4*)&xr[(size_t)warp * C + cbase];
        float4 b = *(const float4*)&We[cbase];
        float4 c = *(const float4*)&att[cbase];
        xrv[0]=a.x; xrv[1]=a.y; xrv[2]=a.z; xrv[3]=a.w;
        wev[0]=b.x; wev[1]=b.y; wev[2]=b.z; wev[3]=b.w;
        attv[0]=c.x; attv[1]=c.y; attv[2]=c.z; attv[3]=c.w;
    } else {
        float2 a = *(const float2*)&xr[(size_t)warp * C + cbase];
        float2 b = *(const float2*)&We[cbase];
        float2 c = *(const float2*)&att[cbase];
        xrv[0]=a.x; xrv[1]=a.y;
        wev[0]=b.x; wev[1]=b.y;
        attv[0]=c.x; attv[1]=c.y;
    }

    float m = -FLT_MAX, s = 0.f;
    float accv[R];
#pragma unroll
    for (int r = 0; r < R; r++) accv[r] = 0.f;

    int beg = g_rowptr[warp], endp = g_rowptr[warp + 1];
    for (int e0 = beg; e0 < endp; e0 += 4) {
        int cnt = endp - e0;
        int jj[4]; float aa[4];
#pragma unroll
        for (int t = 0; t < 4; t++) {
            int ee = (t < cnt) ? e0 + t : e0;
            int2 ce = __ldg(&g_ce[ee]);
            jj[t] = ce.x;
            aa[t] = __int_as_float(ce.y);
        }
        float xlv[4][R];
#pragma unroll
        for (int t = 0; t < 4; t++) {
            if (R == 4) {
                float4 v = *(const float4*)&xl[(size_t)jj[t] * C + cbase];
                xlv[t][0]=v.x; xlv[t][1]=v.y; xlv[t][2]=v.z; xlv[t][3]=v.w;
            } else {
                float2 v = *(const float2*)&xl[(size_t)jj[t] * C + cbase];
                xlv[t][0]=v.x; xlv[t][1]=v.y;
            }
        }
        float part[4];
#pragma unroll
        for (int t = 0; t < 4; t++) {
            float p = 0.f;
#pragma unroll
            for (int r = 0; r < R; r++) {
                float z = xlv[t][r] + xrv[r] + aa[t] * wev[r];
                z = (z > 0.f) ? z : 0.2f * z;     // leaky_relu(0.2)
                p += z * attv[r];
            }
            part[t] = p;
        }
#pragma unroll
        for (int off = 16; off > 0; off >>= 1) {
#pragma unroll
            for (int t = 0; t < 4; t++)
                part[t] += __shfl_xor_sync(0xffffffffu, part[t], off);
        }
#pragma unroll
        for (int t = 0; t < 4; t++)
            if (t >= cnt) part[t] = -FLT_MAX;
        float bm = fmaxf(fmaxf(part[0], part[1]), fmaxf(part[2], part[3]));
        if (bm > m) {
            float c0 = __expf(m - bm);
            s *= c0;
#pragma unroll
            for (int r = 0; r < R; r++) accv[r] *= c0;
            m = bm;
        }
#pragma unroll
        for (int t = 0; t < 4; t++) {
            float w = __expf(part[t] - m);
            s += w;
#pragma unroll
            for (int r = 0; r < R; r++) accv[r] += w * xlv[t][r];
        }
    }

    float inv = 1.0f / (s + 1e-16f);
    float o[R];
#pragma unroll
    for (int r = 0; r < R; r++) {
        float v = accv[r] * inv + bias[cbase + r];
        o[r] = (v > 0.f) ? v : (__expf(v) - 1.0f);   // ELU (fast exp)
    }
    if (R == 4)
        *(float4*)&out[(size_t)warp * C + cbase] = make_float4(o[0], o[1], o[2], o[3]);
    else
        *(float2*)&out[(size_t)warp * C + cbase] = make_float2(o[0], o[1]);
}

// ---------------- host-side setup (static init, pre-baseline) ---------------
namespace {
cudaStream_t g_sB = nullptr;
cudaEvent_t  g_evFork = nullptr, g_evCSR = nullptr, g_evA = nullptr, g_evG2a = nullptr;
bool g_overlap_ok = false;
void *g_pStat = nullptr;
struct EagerLoad {
    EagerLoad() {
        cudaGetSymbolAddress(&g_pStat, g_stat);
        cudaFuncSetAttribute((const void*)mma_gemm_kernel<128>,
                             cudaFuncAttributeMaxDynamicSharedMemorySize, SMEM_M1);
        cudaFuncSetAttribute((const void*)mma_gemm_kernel<64>,
                             cudaFuncAttributeMaxDynamicSharedMemorySize, SMEM_M2);
        bool ok = (cudaStreamCreateWithFlags(&g_sB, cudaStreamNonBlocking) == cudaSuccess);
        ok = ok && (cudaEventCreateWithFlags(&g_evFork, cudaEventDisableTiming) == cudaSuccess);
        ok = ok && (cudaEventCreateWithFlags(&g_evCSR, cudaEventDisableTiming) == cudaSuccess);
        ok = ok && (cudaEventCreateWithFlags(&g_evA, cudaEventDisableTiming) == cudaSuccess);
        ok = ok && (cudaEventCreateWithFlags(&g_evG2a, cudaEventDisableTiming) == cudaSuccess);
        g_overlap_ok = ok;
    }
};
EagerLoad eager_load_instance;
}

// ---------------- launch ----------------------------------------------------
extern "C" void kernel_launch(void* const* d_in, const int* in_sizes, int n_in,
                              void* d_out, int out_size) {
    const float* x    = (const float*)d_in[0];
    const int*   ei   = (const int*)  d_in[1];
    const float* ea   = (const float*)d_in[2];
    const float* Wl1  = (const float*)d_in[3];
    const float* Wr1  = (const float*)d_in[4];
    const float* We1  = (const float*)d_in[5];
    const float* att1 = (const float*)d_in[6];
    const float* b1   = (const float*)d_in[7];
    const float* Wl2  = (const float*)d_in[8];
    const float* Wr2  = (const float*)d_in[9];
    const float* We2  = (const float*)d_in[10];
    const float* att2 = (const float*)d_in[11];
    const float* b2   = (const float*)d_in[12];
    float* out = (float*)d_out;

    int N = in_sizes[0] / H1;       // x is [N,128]
    int E = in_sizes[1] / 2;        // edge_index is [2,E]
    const int* src = ei;
    const int* dst = ei + E;

    float *xl1, *xr1, *h, *xl2, *xr2;
    cudaGetSymbolAddress((void**)&xl1, g_xl1);
    cudaGetSymbolAddress((void**)&xr1, g_xr1);
    cudaGetSymbolAddress((void**)&h,   g_h);
    cudaGetSymbolAddress((void**)&xl2, g_xl2);
    cudaGetSymbolAddress((void**)&xr2, g_xr2);

    int nb = (N + 255) / 256;
    bool ov = g_overlap_ok;
    cudaStream_t sB = ov ? g_sB : (cudaStream_t)0;
    int Nh = (N / 2 + 127) & ~127;  // half split, 128-aligned

    // --- fork: CSR build on side stream, GEMM-1 on main ---
    if (ov) {
        cudaEventRecord(g_evFork, 0);
        cudaStreamWaitEvent(sB, g_evFork, 0);
    }
    // one memset covers stats + lookback state (contiguous in g_stat)
    cudaMemsetAsync(g_pStat, 0, (size_t)(N_MAX + NB_MAX) * sizeof(unsigned long long), sB);
    stats_kernel<<<(E + 255) / 256, 256, 0, sB>>>(dst, ea, E);
    scan_kernel<<<nb, 256, 0, sB>>>(N, E + N);
    scatter_kernel<<<(E + N + 255) / 256, 256, 0, sB>>>(src, dst, ea, E, N);
    if (ov) cudaEventRecord(g_evCSR, sB);

    dim3 gm1(2, (N + 127) / 128);
    mma_gemm_kernel<128><<<gm1, 256, SMEM_M1>>>(x, Wl1, Wr1, xl1, xr1, N, H1);

    if (ov) cudaStreamWaitEvent((cudaStream_t)0, g_evCSR, 0);

    // --- layer 1 aggregate (split halves), pipelined with GEMM-2 ---
    if (ov) {
        gat_node_kernel<H1><<<(Nh + 7) / 8, 256>>>(xl1, xr1, We1, att1, b1, h, 0, Nh);
        cudaEventRecord(g_evA, 0);
        gat_node_kernel<H1><<<(N - Nh + 7) / 8, 256>>>(xl1, xr1, We1, att1, b1, h, Nh, N);

        cudaStreamWaitEvent(sB, g_evA, 0);
        dim3 gma(2, Nh / 128);
        mma_gemm_kernel<64><<<gma, 256, SMEM_M2, sB>>>(h, Wl2, Wr2, xl2, xr2, Nh, H1);
        cudaEventRecord(g_evG2a, sB);

        dim3 gmb(2, (N - Nh + 127) / 128);
        mma_gemm_kernel<64><<<gmb, 256, SMEM_M2>>>(
            h + (size_t)Nh * H1, Wl2, Wr2,
            xl2 + (size_t)Nh * H2, xr2 + (size_t)Nh * H2, N - Nh, H1);
        cudaStreamWaitEvent((cudaStream_t)0, g_evG2a, 0);
    } else {
        gat_node_kernel<H1><<<(N + 7) / 8, 256>>>(xl1, xr1, We1, att1, b1, h, 0, N);
        dim3 gm2(2, (N + 127) / 128);
        mma_gemm_kernel<64><<<gm2, 256, SMEM_M2>>>(h, Wl2, Wr2, xl2, xr2, N, H1);
    }

    gat_node_kernel<H2><<<(N + 7) / 8, 256>>>(xl2, xr2, We2, att2, b2, out, 0, N);
}